// round 6
// baseline (speedup 1.0000x reference)
#include <cuda_runtime.h>
#include <stdint.h>
#include <math.h>

// Problem constants
#define Sdim 512
#define Bdim 16
#define Ddim 2048
#define Hdim 4
#define HDdim 512
#define NB 64
#define Mrows 8192
#define HEAD_ELEMS (Sdim * HDdim)          // 262144
#define ACT_ELEMS ((size_t)Mrows * Ddim)   // 16777216
#define W_ELEMS ((size_t)Ddim * Ddim)      // 4194304

// ---------------- scratch (device globals; no allocation allowed) ----------
__device__ int8_t g_A1[3 * ACT_ELEMS], g_A2[3 * ACT_ELEMS];
__device__ int8_t g_W1[4 * W_ELEMS],  g_W2[4 * W_ELEMS];
__device__ float  g_sAct[3 * Mrows],  g_sW[4 * Ddim];
__device__ float  g_Qh[(size_t)NB * HEAD_ELEMS];
__device__ float  g_Kh[(size_t)NB * HEAD_ELEMS];
__device__ float  g_Vh[(size_t)NB * HEAD_ELEMS];
__device__ float  g_Vt[(size_t)NB * HEAD_ELEMS];
__device__ int8_t g_Q1[(size_t)NB * HEAD_ELEMS], g_Q2[(size_t)NB * HEAD_ELEMS];
__device__ int8_t g_K1[(size_t)NB * HEAD_ELEMS], g_K2[(size_t)NB * HEAD_ELEMS];
__device__ int8_t g_V1[(size_t)NB * HEAD_ELEMS], g_V2[(size_t)NB * HEAD_ELEMS];
__device__ int8_t g_P1[(size_t)NB * HEAD_ELEMS], g_P2[(size_t)NB * HEAD_ELEMS];
__device__ float  g_sQ[NB * Sdim], g_sK[NB * Sdim], g_sV[NB * HDdim], g_sP[NB * Sdim];
__device__ float  g_scores[(size_t)NB * HEAD_ELEMS];
__device__ float  g_attn_fb[(size_t)NB * HEAD_ELEMS];
__device__ float  g_Cperm[ACT_ELEMS];
__device__ int8_t g_C1[ACT_ELEMS], g_C2[ACT_ELEMS];
__device__ float  g_sC[Mrows];

// ---------------- PTX helpers ------------------------------------------------
__device__ __forceinline__ uint32_t smem_u32(const void* p) {
    uint32_t a;
    asm("{ .reg .u64 t; cvta.to.shared.u64 t, %1; cvt.u32.u64 %0, t; }" : "=r"(a) : "l"(p));
    return a;
}
#define CP_ASYNC16(dst, src) \
    asm volatile("cp.async.cg.shared.global [%0], [%1], 16;" :: "r"(dst), "l"(src))
#define CP_COMMIT  asm volatile("cp.async.commit_group;" ::: "memory")
#define CP_WAIT3   asm volatile("cp.async.wait_group 3;" ::: "memory")

__device__ __forceinline__ void ldsm4(uint32_t* r, uint32_t addr) {
    asm volatile("ldmatrix.sync.aligned.m8n8.x4.shared.b16 {%0,%1,%2,%3}, [%4];"
                 : "=r"(r[0]), "=r"(r[1]), "=r"(r[2]), "=r"(r[3]) : "r"(addr));
}
__device__ __forceinline__ void imma(int* c, const uint32_t* a, const uint32_t* b) {
    asm volatile(
        "mma.sync.aligned.m16n8k32.row.col.s32.s8.s8.s32 "
        "{%0,%1,%2,%3}, {%4,%5,%6,%7}, {%8,%9}, {%0,%1,%2,%3};"
        : "+r"(c[0]), "+r"(c[1]), "+r"(c[2]), "+r"(c[3])
        : "r"(a[0]), "r"(a[1]), "r"(a[2]), "r"(a[3]), "r"(b[0]), "r"(b[1]));
}

// ---------------- int8 2-limb NT GEMM ----------------------------------------
// C[M,N] = alpha * sA[m]*sB[n] * (A1*B1 + (A1*B2 + A2*B1)/128)
// Tile 128x128, BK=64 bytes, 256 threads, 8 warps (4m x 2n), warp tile 32x64.
// 5-stage cp.async pipeline (prefetch depth 4), one __syncthreads per chunk.
#define ROW_B 80                       // 64 data + 16 pad
#define TILE_B (128 * ROW_B)           // 10240
#define STAGE_B (4 * TILE_B)           // 40960 (A1,A2,B1,B2)
#define NSTAGE 5
#define GEMM_SMEM (NSTAGE * STAGE_B)   // 204800

enum { EP_F32 = 0, EP_QKV3 = 1 };

// r = s*16 + b, c = h*512 + d  ->  ((b*4+h)*512 + s)*512 + d
__device__ __forceinline__ size_t headperm_idx(int r, int c) {
    int s = r >> 4, bb = r & 15, h = c >> 9, d = c & 511;
    return (((size_t)(bb * Hdim + h) * Sdim + s) * HDdim + d);
}

struct IArgs {
    const int8_t *A1, *A2, *B1, *B2;
    const float *sA, *sB;
    int ssA, ssB;            // scale entries per z
    int K;                   // bytes per operand row (lda == ldb == K)
    int ldc;
    size_t bsA, bsB, bsC;    // per-z strides (A/B in bytes, C in elements)
    float *Cf, *Cf1, *Cf2;   // EP_F32: Cf; EP_QKV3: z0->Cf, z1->Cf1, z2->Cf2
    float alpha;
    int mode;
};

__global__ __launch_bounds__(256, 1)
void imma_gemm(IArgs g)
{
    extern __shared__ char smraw[];
    const uint32_t sb = smem_u32(smraw);
    const int tid = threadIdx.x;
    const int lane = tid & 31;
    const int wid = tid >> 5;
    const int wm = wid & 3;            // 0..3
    const int wn = wid >> 2;           // 0..1
    const int m0 = blockIdx.y * 128;
    const int n0 = blockIdx.x * 128;
    const size_t z = blockIdx.z;

    const int8_t* A1 = g.A1 + z * g.bsA;
    const int8_t* A2 = g.A2 + z * g.bsA;
    const int8_t* B1 = g.B1 + z * g.bsB;
    const int8_t* B2 = g.B2 + z * g.bsB;
    const float* sAz = g.sA + z * g.ssA;
    const float* sBz = g.sB + z * g.ssB;

    int acc1[2][8][4], accm[2][8][4];
#pragma unroll
    for (int i = 0; i < 2; i++)
#pragma unroll
        for (int j = 0; j < 8; j++)
#pragma unroll
            for (int x = 0; x < 4; x++) { acc1[i][j][x] = 0; accm[i][j][x] = 0; }

    // ldmatrix per-thread addressing (byte offsets within 80B rows)
    const uint32_t a_row = (uint32_t)(wm * 32) + (lane & 15);
    const uint32_t a_kb  = (uint32_t)((lane >> 4) * 16);
    const uint32_t b_row = (uint32_t)(wn * 64) + (lane & 7) + (((lane >> 4) & 1) << 3);
    const uint32_t b_kb  = (uint32_t)(((lane >> 3) & 1) * 16);

    const int K = g.K;
    const int NCH = K >> 6;

    auto issue = [&](int ch, int stg) {
        const int kOff = ch * 64;
        const uint32_t stb = sb + (uint32_t)stg * STAGE_B;
#pragma unroll
        for (int j = 0; j < 2; j++) {
            int id = tid + j * 256;          // 0..511
            int row = id >> 2;               // 0..127
            int cc = id & 3;                 // 16B chunk in 64B row
            uint32_t doff = (uint32_t)row * ROW_B + (uint32_t)cc * 16;
            size_t soA = (size_t)(m0 + row) * K + kOff + cc * 16;
            size_t soB = (size_t)(n0 + row) * K + kOff + cc * 16;
            CP_ASYNC16(stb + doff,              A1 + soA);
            CP_ASYNC16(stb + TILE_B + doff,     A2 + soA);
            CP_ASYNC16(stb + 2 * TILE_B + doff, B1 + soB);
            CP_ASYNC16(stb + 3 * TILE_B + doff, B2 + soB);
        }
        CP_COMMIT;
    };

    auto compute = [&](int stg) {
        const uint32_t stb = sb + (uint32_t)stg * STAGE_B;
        const uint32_t a1B = stb;
        const uint32_t a2B = stb + TILE_B;
        const uint32_t b1B = stb + 2 * TILE_B;
        const uint32_t b2B = stb + 3 * TILE_B;
#pragma unroll
        for (int ks = 0; ks < 2; ks++) {       // two k32 steps per 64B chunk
            uint32_t a1f[2][4], a2f[2][4];
#pragma unroll
            for (int i = 0; i < 2; i++) {
                uint32_t off = (a_row + (uint32_t)(i * 16)) * ROW_B + (uint32_t)(ks * 32) + a_kb;
                ldsm4(a1f[i], a1B + off);
                ldsm4(a2f[i], a2B + off);
            }
#pragma unroll
            for (int g2 = 0; g2 < 4; g2++) {   // groups of 2 n8-tiles
                uint32_t b1f[4], b2f[4];
                uint32_t off = (b_row + (uint32_t)(g2 * 16)) * ROW_B + (uint32_t)(ks * 32) + b_kb;
                ldsm4(b1f, b1B + off);
                ldsm4(b2f, b2B + off);
#pragma unroll
                for (int i = 0; i < 2; i++)
#pragma unroll
                    for (int jj = 0; jj < 2; jj++)
                        imma(acc1[i][g2 * 2 + jj], a1f[i], b1f + jj * 2);
#pragma unroll
                for (int i = 0; i < 2; i++)
#pragma unroll
                    for (int jj = 0; jj < 2; jj++)
                        imma(accm[i][g2 * 2 + jj], a1f[i], b2f + jj * 2);
#pragma unroll
                for (int i = 0; i < 2; i++)
#pragma unroll
                    for (int jj = 0; jj < 2; jj++)
                        imma(accm[i][g2 * 2 + jj], a2f[i], b1f + jj * 2);
            }
        }
    };

    issue(0, 0); issue(1, 1); issue(2, 2); issue(3, 3);
    for (int ch = 0; ch < NCH; ch++) {
        CP_WAIT3;                 // group ch complete (<=3 pending)
        __syncthreads();          // compute(ch-1) finished -> slot (ch+4)%5 reusable
        if (ch + 4 < NCH) issue(ch + 4, (ch + 4) % NSTAGE);
        compute(ch % NSTAGE);
    }

    // -------- epilogue --------
    const int quad = lane >> 2, tq = lane & 3;
    const float alpha = g.alpha;
#pragma unroll
    for (int i = 0; i < 2; i++) {
        const int r = m0 + wm * 32 + i * 16 + quad;
        const float sa0 = sAz[r] * alpha;
        const float sa1 = sAz[r + 8] * alpha;
#pragma unroll
        for (int jj = 0; jj < 8; jj++) {
            const int c = n0 + wn * 64 + jj * 8 + tq * 2;
            const float sb0 = sBz[c];
            const float sb1 = sBz[c + 1];
            const float v0 = ((float)acc1[i][jj][0] + (float)accm[i][jj][0] * 0.0078125f) * sa0 * sb0;
            const float v1 = ((float)acc1[i][jj][1] + (float)accm[i][jj][1] * 0.0078125f) * sa0 * sb1;
            const float v2 = ((float)acc1[i][jj][2] + (float)accm[i][jj][2] * 0.0078125f) * sa1 * sb0;
            const float v3 = ((float)acc1[i][jj][3] + (float)accm[i][jj][3] * 0.0078125f) * sa1 * sb1;
            if (g.mode == EP_F32) {
                float2 a0; a0.x = v0; a0.y = v1;
                float2 a1; a1.x = v2; a1.y = v3;
                *(float2*)(g.Cf + z * g.bsC + (size_t)r * g.ldc + c) = a0;
                *(float2*)(g.Cf + z * g.bsC + (size_t)(r + 8) * g.ldc + c) = a1;
            } else {
                float* dst = (z == 0) ? g.Cf : (z == 1) ? g.Cf1 : g.Cf2;
                float2 a0; a0.x = v0; a0.y = v1;
                float2 a1; a1.x = v2; a1.y = v3;
                *(float2*)(dst + headperm_idx(r, c)) = a0;
                *(float2*)(dst + headperm_idx(r + 8, c)) = a1;
            }
        }
    }
}

// ---------------- per-row quantization: x = s*(q1 + q2/128) ------------------
// One warp per row of width W = N4*128 floats.
template <int N4>
__global__ void quant_rows(const float* __restrict__ x, int8_t* __restrict__ q1,
                           int8_t* __restrict__ q2, float* __restrict__ scl, int nrows)
{
    int gw = (blockIdx.x * blockDim.x + threadIdx.x) >> 5;
    int lane = threadIdx.x & 31;
    if (gw >= nrows) return;
    const float4* row = (const float4*)(x + (size_t)gw * (N4 * 128));
    float4 v[N4];
    float m = 0.f;
#pragma unroll
    for (int j = 0; j < N4; j++) {
        v[j] = row[lane + j * 32];
        m = fmaxf(m, fmaxf(fmaxf(fabsf(v[j].x), fabsf(v[j].y)),
                           fmaxf(fabsf(v[j].z), fabsf(v[j].w))));
    }
#pragma unroll
    for (int o = 16; o > 0; o >>= 1) m = fmaxf(m, __shfl_xor_sync(0xffffffffu, m, o));
    const float inv = (m > 0.f) ? 127.0f / m : 0.f;
    if (lane == 0) scl[gw] = (m > 0.f) ? m * (1.0f / 127.0f) : 1.0f;

    int8_t* q1r = q1 + (size_t)gw * (N4 * 128);
    int8_t* q2r = q2 + (size_t)gw * (N4 * 128);
#pragma unroll
    for (int j = 0; j < N4; j++) {
        float f[4] = {v[j].x * inv, v[j].y * inv, v[j].z * inv, v[j].w * inv};
        char c1[4], c2[4];
#pragma unroll
        for (int e = 0; e < 4; e++) {
            int i1 = __float2int_rn(f[e]);
            int i2 = __float2int_rn((f[e] - (float)i1) * 128.0f);
            c1[e] = (char)i1; c2[e] = (char)i2;
        }
        int idx = (lane + j * 32) * 4;
        *(char4*)(q1r + idx) = make_char4(c1[0], c1[1], c1[2], c1[3]);
        *(char4*)(q2r + idx) = make_char4(c2[0], c2[1], c2[2], c2[3]);
    }
}

// ---------------- V transpose (fp32): Vh[gb][t][d] -> Vt[gb][d][t] -----------
__global__ void vtrans_kernel(const float* __restrict__ Vh, float* __restrict__ Vt)
{
    __shared__ float tile[32][33];
    const int gb = blockIdx.z;
    const int t0 = blockIdx.x * 32;
    const int d0 = blockIdx.y * 32;
    const int tx = threadIdx.x, ty = threadIdx.y;     // 32 x 8
    const float* src = Vh + (size_t)gb * HEAD_ELEMS;
#pragma unroll
    for (int i = 0; i < 32; i += 8)
        tile[ty + i][tx] = src[(size_t)(t0 + ty + i) * HDdim + d0 + tx];
    __syncthreads();
    float* dst = Vt + (size_t)gb * HEAD_ELEMS;
#pragma unroll
    for (int i = 0; i < 32; i += 8)
        dst[(size_t)(d0 + ty + i) * Sdim + t0 + tx] = tile[tx][ty + i];
}

// ---------------- softmax + P quantization ----------------------------------
// One warp per row; lane handles 16 CONSECUTIVE elements (int8 stores coalesce).
__global__ void softmax_kernel(const float* __restrict__ scores,
                               float* __restrict__ attn,
                               int8_t* __restrict__ P1, int8_t* __restrict__ P2,
                               float* __restrict__ sP)
{
    int gwarp = (blockIdx.x * blockDim.x + threadIdx.x) >> 5;
    int lane  = threadIdx.x & 31;
    if (gwarp >= NB * Sdim) return;
    int gb = gwarp >> 9;       // b*4+h
    int s  = gwarp & 511;
    int b  = gb >> 2;
    int h  = gb & 3;

    const float4* row = (const float4*)(scores + ((size_t)gb * Sdim + s) * Sdim);
    float4 v[4];
    float mx = -1e30f;
#pragma unroll
    for (int j = 0; j < 4; j++) {
        v[j] = row[lane * 4 + j];
        mx = fmaxf(mx, fmaxf(fmaxf(v[j].x, v[j].y), fmaxf(v[j].z, v[j].w)));
    }
#pragma unroll
    for (int o = 16; o > 0; o >>= 1) mx = fmaxf(mx, __shfl_xor_sync(0xffffffffu, mx, o));
    float vals[16];
    float sum = 0.f;
#pragma unroll
    for (int j = 0; j < 4; j++) {
        vals[j * 4 + 0] = expf(v[j].x - mx);
        vals[j * 4 + 1] = expf(v[j].y - mx);
        vals[j * 4 + 2] = expf(v[j].z - mx);
        vals[j * 4 + 3] = expf(v[j].w - mx);
        sum += vals[j * 4 + 0] + vals[j * 4 + 1] + vals[j * 4 + 2] + vals[j * 4 + 3];
    }
#pragma unroll
    for (int o = 16; o > 0; o >>= 1) sum += __shfl_xor_sync(0xffffffffu, sum, o);
    const float inv = 1.f / sum;

    // attn output (b,s,h,t)
    float4* arow = (float4*)(attn + (((size_t)b * Sdim + s) * Hdim + h) * HDdim);
#pragma unroll
    for (int j = 0; j < 4; j++) {
        float4 p;
        p.x = vals[j * 4 + 0] * inv; p.y = vals[j * 4 + 1] * inv;
        p.z = vals[j * 4 + 2] * inv; p.w = vals[j * 4 + 3] * inv;
        arow[lane * 4 + j] = p;
    }
    // P quantization: max prob = inv (exp(mx-mx)=1), scale = inv/127, p/s = vals*127
    if (lane == 0) sP[gwarp] = inv * (1.0f / 127.0f);
    int8_t* p1r = P1 + ((size_t)gb * Sdim + s) * Sdim;
    int8_t* p2r = P2 + ((size_t)gb * Sdim + s) * Sdim;
#pragma unroll
    for (int j = 0; j < 4; j++) {
        char c1[4], c2[4];
#pragma unroll
        for (int e = 0; e < 4; e++) {
            float f = vals[j * 4 + e] * 127.0f;
            int i1 = __float2int_rn(f);
            int i2 = __float2int_rn((f - (float)i1) * 128.0f);
            c1[e] = (char)i1; c2[e] = (char)i2;
        }
        int idx = lane * 16 + j * 4;
        *(char4*)(p1r + idx) = make_char4(c1[0], c1[1], c1[2], c1[3]);
        *(char4*)(p2r + idx) = make_char4(c2[0], c2[1], c2[2], c2[3]);
    }
}

// ---------------- launch -----------------------------------------------------
extern "C" void kernel_launch(void* const* d_in, const int* in_sizes, int n_in,
                              void* d_out, int out_size)
{
    const float* q  = (const float*)d_in[0];
    const float* k  = (const float*)d_in[1];
    const float* v  = (const float*)d_in[2];
    const float* Wq = (const float*)d_in[3];
    const float* Wk = (const float*)d_in[4];
    const float* Wv = (const float*)d_in[5];
    const float* Wo = (const float*)d_in[6];
    float* out = (float*)d_out;

    int8_t *A1, *A2, *W1, *W2, *Q1, *Q2, *K1, *K2, *V1, *V2, *P1, *P2, *C1, *C2;
    float *sAct, *sW, *sQ, *sK, *sV, *sP, *sC;
    float *Qh, *Kh, *Vh, *Vt, *Sc, *At, *Cp;
    cudaGetSymbolAddress((void**)&A1, g_A1);   cudaGetSymbolAddress((void**)&A2, g_A2);
    cudaGetSymbolAddress((void**)&W1, g_W1);   cudaGetSymbolAddress((void**)&W2, g_W2);
    cudaGetSymbolAddress((void**)&sAct, g_sAct); cudaGetSymbolAddress((void**)&sW, g_sW);
    cudaGetSymbolAddress((void**)&Qh, g_Qh);   cudaGetSymbolAddress((void**)&Kh, g_Kh);
    cudaGetSymbolAddress((void**)&Vh, g_Vh);   cudaGetSymbolAddress((void**)&Vt, g_Vt);
    cudaGetSymbolAddress((void**)&Q1, g_Q1);   cudaGetSymbolAddress((void**)&Q2, g_Q2);
    cudaGetSymbolAddress((void**)&K1, g_K1);   cudaGetSymbolAddress((void**)&K2, g_K2);
    cudaGetSymbolAddress((void**)&V1, g_V1);   cudaGetSymbolAddress((void**)&V2, g_V2);
    cudaGetSymbolAddress((void**)&P1, g_P1);   cudaGetSymbolAddress((void**)&P2, g_P2);
    cudaGetSymbolAddress((void**)&sQ, g_sQ);   cudaGetSymbolAddress((void**)&sK, g_sK);
    cudaGetSymbolAddress((void**)&sV, g_sV);   cudaGetSymbolAddress((void**)&sP, g_sP);
    cudaGetSymbolAddress((void**)&Sc, g_scores); cudaGetSymbolAddress((void**)&At, g_attn_fb);
    cudaGetSymbolAddress((void**)&Cp, g_Cperm);
    cudaGetSymbolAddress((void**)&C1, g_C1);   cudaGetSymbolAddress((void**)&C2, g_C2);
    cudaGetSymbolAddress((void**)&sC, g_sC);

    const long MAIN_OUT = (long)Mrows * Ddim;
    float* attn_out = ((long)out_size >= 2 * MAIN_OUT) ? (out + MAIN_OUT) : At;

    cudaFuncSetAttribute(imma_gemm, cudaFuncAttributeMaxDynamicSharedMemorySize, GEMM_SMEM);

    dim3 qblk(256);
    // weight quantization (rows = 2048; 8 warps/block -> 256 blocks)
    quant_rows<16><<<256, qblk>>>(Wq, W1 + 0 * W_ELEMS, W2 + 0 * W_ELEMS, sW + 0 * Ddim, Ddim);
    quant_rows<16><<<256, qblk>>>(Wk, W1 + 1 * W_ELEMS, W2 + 1 * W_ELEMS, sW + 1 * Ddim, Ddim);
    quant_rows<16><<<256, qblk>>>(Wv, W1 + 2 * W_ELEMS, W2 + 2 * W_ELEMS, sW + 2 * Ddim, Ddim);
    quant_rows<16><<<256, qblk>>>(Wo, W1 + 3 * W_ELEMS, W2 + 3 * W_ELEMS, sW + 3 * Ddim, Ddim);
    // activation quantization (rows = 8192 each)
    quant_rows<16><<<1024, qblk>>>(q, A1 + 0 * ACT_ELEMS, A2 + 0 * ACT_ELEMS, sAct + 0 * Mrows, Mrows);
    quant_rows<16><<<1024, qblk>>>(k, A1 + 1 * ACT_ELEMS, A2 + 1 * ACT_ELEMS, sAct + 1 * Mrows, Mrows);
    quant_rows<16><<<1024, qblk>>>(v, A1 + 2 * ACT_ELEMS, A2 + 2 * ACT_ELEMS, sAct + 2 * Mrows, Mrows);

    dim3 gblk(256);
    // fused Q/K/V projection -> fp32 head-permuted
    {
        IArgs a;
        a.A1 = A1; a.A2 = A2; a.B1 = W1; a.B2 = W2;
        a.sA = sAct; a.sB = sW; a.ssA = Mrows; a.ssB = Ddim;
        a.K = Ddim; a.ldc = Ddim;
        a.bsA = ACT_ELEMS; a.bsB = W_ELEMS; a.bsC = 0;
        a.Cf = Qh; a.Cf1 = Kh; a.Cf2 = Vh;
        a.alpha = 1.0f; a.mode = EP_QKV3;
        dim3 grid(Ddim / 128, Mrows / 128, 3);     // 16 x 64 x 3
        imma_gemm<<<grid, gblk, GEMM_SMEM>>>(a);
    }
    // quantize Q, K head rows (32768 rows of 512)
    quant_rows<4><<<4096, qblk>>>(Qh, Q1, Q2, sQ, NB * Sdim);
    quant_rows<4><<<4096, qblk>>>(Kh, K1, K2, sK, NB * Sdim);
    // V transpose + quantize
    {
        dim3 tb(32, 8), tg(Sdim / 32, HDdim / 32, NB);
        vtrans_kernel<<<tg, tb>>>(Vh, Vt);
    }
    quant_rows<4><<<4096, qblk>>>(Vt, V1, V2, sV, NB * HDdim);
    // scores = Q K^T / sqrt(hd)
    {
        IArgs a;
        a.A1 = Q1; a.A2 = Q2; a.B1 = K1; a.B2 = K2;
        a.sA = sQ; a.sB = sK; a.ssA = Sdim; a.ssB = Sdim;
        a.K = HDdim; a.ldc = Sdim;
        a.bsA = HEAD_ELEMS; a.bsB = HEAD_ELEMS; a.bsC = HEAD_ELEMS;
        a.Cf = Sc; a.Cf1 = nullptr; a.Cf2 = nullptr;
        a.alpha = 0.044194173824159223f;
        a.mode = EP_F32;
        dim3 grid(Sdim / 128, Sdim / 128, NB);     // 4 x 4 x 64
        imma_gemm<<<grid, gblk, GEMM_SMEM>>>(a);
    }
    // softmax -> attn output + P limbs
    softmax_kernel<<<(NB * Sdim * 32) / 256, 256>>>(Sc, attn_out, P1, P2, sP);
    // context = P V^T -> Cperm (b,h,s,d)
    {
        IArgs a;
        a.A1 = P1; a.A2 = P2; a.B1 = V1; a.B2 = V2;
        a.sA = sP; a.sB = sV; a.ssA = Sdim; a.ssB = HDdim;
        a.K = Sdim; a.ldc = HDdim;
        a.bsA = HEAD_ELEMS; a.bsB = HEAD_ELEMS; a.bsC = HEAD_ELEMS;
        a.Cf = Cp; a.Cf1 = nullptr; a.Cf2 = nullptr;
        a.alpha = 1.0f; a.mode = EP_F32;
        dim3 grid(HDdim / 128, Sdim / 128, NB);    // 4 x 4 x 64
        imma_gemm<<<grid, gblk, GEMM_SMEM>>>(a);
    }
    // quantize context rows (8192 x 2048)
    quant_rows<16><<<1024, qblk>>>(Cp, C1, C2, sC, Mrows);
    // output = C @ Wo^T
    {
        IArgs a;
        a.A1 = C1; a.A2 = C2; a.B1 = W1 + 3 * W_ELEMS; a.B2 = W2 + 3 * W_ELEMS;
        a.sA = sC; a.sB = sW + 3 * Ddim; a.ssA = 0; a.ssB = 0;
        a.K = Ddim; a.ldc = Ddim;
        a.bsA = 0; a.bsB = 0; a.bsC = 0;
        a.Cf = out; a.Cf1 = nullptr; a.Cf2 = nullptr;
        a.alpha = 1.0f; a.mode = EP_F32;
        dim3 grid(Ddim / 128, Mrows / 128, 1);     // 16 x 64
        imma_gemm<<<grid, gblk, GEMM_SMEM>>>(a);
    }
}

// round 7
// speedup vs baseline: 3.4925x; 3.4925x over previous
#include <cuda_runtime.h>
#include <cuda_fp16.h>
#include <stdint.h>
#include <math.h>

// Problem constants
#define Sdim 512
#define Bdim 16
#define Ddim 2048
#define Hdim 4
#define HDdim 512
#define NB 64
#define Mrows 8192
#define HEAD_ELEMS (Sdim * HDdim)          // 262144
#define ACT_ELEMS ((size_t)Mrows * Ddim)   // 16777216
#define W_ELEMS ((size_t)Ddim * Ddim)      // 4194304

// ---------------- scratch (device globals; no allocation allowed) ----------
__device__ __half g_Act[3 * ACT_ELEMS];                    // activations, single fp16
__device__ __half g_Whi[4 * W_ELEMS], g_Wlo[4 * W_ELEMS];  // weights, 2 limbs
__device__ __half g_Q1[(size_t)NB * HEAD_ELEMS];           // Q single
__device__ __half g_Khi[(size_t)NB * HEAD_ELEMS], g_Klo[(size_t)NB * HEAD_ELEMS];
__device__ float  g_Vh[(size_t)NB * HEAD_ELEMS];
__device__ __half g_Vthi[(size_t)NB * HEAD_ELEMS], g_Vtlo[(size_t)NB * HEAD_ELEMS];
__device__ float  g_scores[(size_t)NB * HEAD_ELEMS];
__device__ float  g_attn_fb[(size_t)NB * HEAD_ELEMS];
__device__ __half g_P1[(size_t)NB * HEAD_ELEMS];           // P single
__device__ __half g_C1[ACT_ELEMS];                         // context single

// ---------------- PTX helpers ------------------------------------------------
__device__ __forceinline__ uint32_t smem_u32(const void* p) {
    uint32_t a;
    asm("{ .reg .u64 t; cvta.to.shared.u64 t, %1; cvt.u32.u64 %0, t; }" : "=r"(a) : "l"(p));
    return a;
}
#define CP_ASYNC16(dst, src) \
    asm volatile("cp.async.cg.shared.global [%0], [%1], 16;" :: "r"(dst), "l"(src))
#define CP_COMMIT  asm volatile("cp.async.commit_group;" ::: "memory")
#define CP_WAIT0   asm volatile("cp.async.wait_group 0;" ::: "memory")
#define CP_WAIT1   asm volatile("cp.async.wait_group 1;" ::: "memory")

__device__ __forceinline__ void ldsm4(uint32_t* r, uint32_t addr) {
    asm volatile("ldmatrix.sync.aligned.m8n8.x4.shared.b16 {%0,%1,%2,%3}, [%4];"
                 : "=r"(r[0]), "=r"(r[1]), "=r"(r[2]), "=r"(r[3]) : "r"(addr));
}
__device__ __forceinline__ void mma_f16(float* c, const uint32_t* a, const uint32_t* b) {
    asm volatile(
        "mma.sync.aligned.m16n8k16.row.col.f32.f16.f16.f32 "
        "{%0,%1,%2,%3}, {%4,%5,%6,%7}, {%8,%9}, {%0,%1,%2,%3};"
        : "+f"(c[0]), "+f"(c[1]), "+f"(c[2]), "+f"(c[3])
        : "r"(a[0]), "r"(a[1]), "r"(a[2]), "r"(a[3]), "r"(b[0]), "r"(b[1]));
}

__device__ __forceinline__ void wr_h2(__half* H, size_t off, float a, float b) {
    __half2 h; h.x = __float2half(a); h.y = __float2half(b);
    *(__half2*)(H + off) = h;
}
__device__ __forceinline__ void wr_hl2(__half* H, __half* L, size_t off, float a, float b) {
    __half ha = __float2half(a), hb = __float2half(b);
    __half2 hv; hv.x = ha; hv.y = hb;
    __half2 lv;
    lv.x = __float2half(a - __half2float(ha));
    lv.y = __float2half(b - __half2float(hb));
    *(__half2*)(H + off) = hv;
    *(__half2*)(L + off) = lv;
}

// ---------------- fp16 2-pass NT GEMM ----------------------------------------
// C[M,N] = alpha * A[M,K] * (Bhi + Blo)[N,K]^T ; A single fp16, B two limbs.
// Tile 128x256, BK=32, 512 threads (16 warps, 4m x 4n, warp 32x64).
// 3-stage cp.async pipeline, one __syncthreads per chunk. (R5-validated frame.)
#define ROW_B 80                        // 32 fp16 = 64B data + 16 pad
#define A_TILE_B (128 * ROW_B)          // 10240
#define B_TILE_B (256 * ROW_B)          // 20480
#define STAGE_B (A_TILE_B + 2 * B_TILE_B)   // 51200
#define NSTAGE 3
#define GEMM_SMEM (NSTAGE * STAGE_B)    // 153600

enum { EP_F32 = 0, EP_HALF = 1, EP_QKV3 = 2 };

// r = s*16 + b, c = h*512 + d  ->  ((b*4+h)*512 + s)*512 + d
__device__ __forceinline__ size_t headperm_idx(int r, int c) {
    int s = r >> 4, bb = r & 15, h = c >> 9, d = c & 511;
    return (((size_t)(bb * Hdim + h) * Sdim + s) * HDdim + d);
}

struct HArgs {
    const __half *A, *Bhi, *Blo;
    int K, ldc;
    size_t bsA, bsB, bsC;
    float* Cf;                 // EP_F32 dst ; EP_QKV3 z==2 (V, fp32)
    __half* Ch;                // EP_HALF dst ; EP_QKV3 z==0 (Q single)
    __half *Khi, *Klo;         // EP_QKV3 z==1 (K limbs)
    float alpha;
    int mode;
};

__global__ __launch_bounds__(512, 1)
void hgemm(HArgs g)
{
    extern __shared__ char smraw[];
    const uint32_t sb = smem_u32(smraw);
    const int tid = threadIdx.x;
    const int lane = tid & 31;
    const int wid = tid >> 5;
    const int wm = wid & 3;
    const int wn = wid >> 2;
    const int m0 = blockIdx.y * 128;
    const int n0 = blockIdx.x * 256;
    const size_t z = blockIdx.z;

    const __half* A  = g.A + z * g.bsA;
    const __half* Bh = g.Bhi + z * g.bsB;
    const __half* Bl = g.Blo + z * g.bsB;

    float acc[2][8][4];
#pragma unroll
    for (int i = 0; i < 2; i++)
#pragma unroll
        for (int j = 0; j < 8; j++)
#pragma unroll
            for (int x = 0; x < 4; x++) acc[i][j][x] = 0.f;

    const uint32_t a_mrow = (uint32_t)(wm * 32) + (lane & 15);
    const uint32_t a_kadd = (uint32_t)(((lane >> 4) & 1) << 3);
    const uint32_t b_nrow = (uint32_t)(wn * 64) + (lane & 7) + (((lane >> 4) & 1) << 3);
    const uint32_t b_kadd = (uint32_t)(((lane >> 3) & 1) << 3);

    const int la_row = tid >> 2;
    const int la_cc  = tid & 3;
    const int K = g.K;
    const int NCH = K >> 5;

    auto issue = [&](int ch, int stg) {
        const int kOff = ch * 32;
        const uint32_t stb = sb + (uint32_t)stg * STAGE_B;
        {   // A: 512 chunks, 1/thread
            uint32_t d = stb + (uint32_t)la_row * ROW_B + (uint32_t)la_cc * 16;
            CP_ASYNC16(d, A + (size_t)(m0 + la_row) * K + kOff + la_cc * 8);
        }
#pragma unroll
        for (int j = 0; j < 2; j++) {   // B hi/lo: 1024 chunks each, 2/thread
            int id = tid + j * 512;
            int row = id >> 2;
            int cc = id & 3;
            uint32_t d = stb + A_TILE_B + (uint32_t)row * ROW_B + (uint32_t)cc * 16;
            const size_t so = (size_t)(n0 + row) * K + kOff + cc * 8;
            CP_ASYNC16(d, Bh + so);
            CP_ASYNC16(d + B_TILE_B, Bl + so);
        }
        CP_COMMIT;
    };

    auto compute = [&](int stg) {
        const uint32_t stb = sb + (uint32_t)stg * STAGE_B;
        const uint32_t aB  = stb;
        const uint32_t bhB = stb + A_TILE_B;
        const uint32_t blB = stb + A_TILE_B + B_TILE_B;
#pragma unroll
        for (int ks = 0; ks < 2; ks++) {
            uint32_t af[2][4];
#pragma unroll
            for (int i = 0; i < 2; i++) {
                uint32_t off = (a_mrow + (uint32_t)(i * 16)) * ROW_B +
                               ((uint32_t)(ks * 16) + a_kadd) * 2;
                ldsm4(af[i], aB + off);
            }
#pragma unroll
            for (int g2 = 0; g2 < 4; g2++) {
                uint32_t bfh[4], bfl[4];
                uint32_t off = (b_nrow + (uint32_t)(g2 * 16)) * ROW_B +
                               ((uint32_t)(ks * 16) + b_kadd) * 2;
                ldsm4(bfh, bhB + off);
                ldsm4(bfl, blB + off);
#pragma unroll
                for (int i = 0; i < 2; i++)
#pragma unroll
                    for (int jj = 0; jj < 2; jj++)
                        mma_f16(acc[i][g2 * 2 + jj], af[i], bfh + jj * 2);
#pragma unroll
                for (int i = 0; i < 2; i++)
#pragma unroll
                    for (int jj = 0; jj < 2; jj++)
                        mma_f16(acc[i][g2 * 2 + jj], af[i], bfl + jj * 2);
            }
        }
    };

    issue(0, 0);
    issue(1, 1);
    for (int ch = 0; ch < NCH; ch++) {
        CP_WAIT1;
        __syncthreads();
        if (ch + 2 < NCH) issue(ch + 2, (ch + 2) % NSTAGE);
        compute(ch % NSTAGE);
    }

    // -------- epilogue --------
    const int quad = lane >> 2, tq = lane & 3;
    const float alpha = g.alpha;
#pragma unroll
    for (int i = 0; i < 2; i++) {
#pragma unroll
        for (int jj = 0; jj < 8; jj++) {
            const int r = m0 + wm * 32 + i * 16 + quad;
            const int c = n0 + wn * 64 + jj * 8 + tq * 2;
            const float v0 = acc[i][jj][0] * alpha;
            const float v1 = acc[i][jj][1] * alpha;
            const float v2 = acc[i][jj][2] * alpha;
            const float v3 = acc[i][jj][3] * alpha;
            if (g.mode == EP_F32) {
                float2 a0; a0.x = v0; a0.y = v1;
                float2 a1; a1.x = v2; a1.y = v3;
                *(float2*)(g.Cf + z * g.bsC + (size_t)r * g.ldc + c) = a0;
                *(float2*)(g.Cf + z * g.bsC + (size_t)(r + 8) * g.ldc + c) = a1;
            } else if (g.mode == EP_HALF) {
                wr_h2(g.Ch, z * g.bsC + (size_t)r * g.ldc + c, v0, v1);
                wr_h2(g.Ch, z * g.bsC + (size_t)(r + 8) * g.ldc + c, v2, v3);
            } else {  // EP_QKV3
                size_t o0 = headperm_idx(r, c), o1 = headperm_idx(r + 8, c);
                if (z == 0) {
                    wr_h2(g.Ch, o0, v0, v1);
                    wr_h2(g.Ch, o1, v2, v3);
                } else if (z == 1) {
                    wr_hl2(g.Khi, g.Klo, o0, v0, v1);
                    wr_hl2(g.Khi, g.Klo, o1, v2, v3);
                } else {
                    float2 a0; a0.x = v0; a0.y = v1;
                    float2 a1; a1.x = v2; a1.y = v3;
                    *(float2*)(g.Cf + o0) = a0;
                    *(float2*)(g.Cf + o1) = a1;
                }
            }
        }
    }
}

// ---------------- fp32 -> fp16 single (q,k,v combined, z picks) --------------
__global__ void cvt_acts(const float* __restrict__ q, const float* __restrict__ k,
                         const float* __restrict__ v, __half* __restrict__ dst, int n4)
{
    int i = blockIdx.x * blockDim.x + threadIdx.x;
    if (i >= n4) return;
    const int zz = blockIdx.z;
    const float* x = (zz == 0) ? q : (zz == 1) ? k : v;
    float4 vv = ((const float4*)x)[i];
    __half2 h0, h1;
    h0.x = __float2half(vv.x); h0.y = __float2half(vv.y);
    h1.x = __float2half(vv.z); h1.y = __float2half(vv.w);
    __half2* d = (__half2*)(dst + (size_t)zz * ACT_ELEMS);
    d[i * 2 + 0] = h0;
    d[i * 2 + 1] = h1;
}

// ---------------- fp32 -> fp16 hi/lo (weights) -------------------------------
__global__ void cvt_w(const float* __restrict__ x, __half* __restrict__ hi,
                      __half* __restrict__ lo, int n4)
{
    int i = blockIdx.x * blockDim.x + threadIdx.x;
    if (i >= n4) return;
    float4 v = ((const float4*)x)[i];
    float f[4] = {v.x, v.y, v.z, v.w};
    __half2 h2[2], l2[2];
#pragma unroll
    for (int j = 0; j < 2; j++) {
        __half ha = __float2half(f[j * 2 + 0]);
        __half hb = __float2half(f[j * 2 + 1]);
        h2[j].x = ha; h2[j].y = hb;
        l2[j].x = __float2half(f[j * 2 + 0] - __half2float(ha));
        l2[j].y = __float2half(f[j * 2 + 1] - __half2float(hb));
    }
    ((__half2*)hi)[i * 2 + 0] = h2[0];
    ((__half2*)hi)[i * 2 + 1] = h2[1];
    ((__half2*)lo)[i * 2 + 0] = l2[0];
    ((__half2*)lo)[i * 2 + 1] = l2[1];
}

// ---------------- V transpose + fp16 hi/lo split -----------------------------
__global__ void vtrans_kernel(const float* __restrict__ Vh,
                              __half* __restrict__ Vthi, __half* __restrict__ Vtlo)
{
    __shared__ float tile[32][33];
    const int gb = blockIdx.z;
    const int t0 = blockIdx.x * 32;
    const int d0 = blockIdx.y * 32;
    const int tx = threadIdx.x, ty = threadIdx.y;   // 32 x 8
    const float* src = Vh + (size_t)gb * HEAD_ELEMS;
#pragma unroll
    for (int i = 0; i < 32; i += 8)
        tile[ty + i][tx] = src[(size_t)(t0 + ty + i) * HDdim + d0 + tx];
    __syncthreads();
    __half* dh = Vthi + (size_t)gb * HEAD_ELEMS;
    __half* dl = Vtlo + (size_t)gb * HEAD_ELEMS;
#pragma unroll
    for (int i = 0; i < 32; i += 8) {
        float v = tile[tx][ty + i];
        __half h = __float2half(v);
        size_t o = (size_t)(d0 + ty + i) * Sdim + t0 + tx;
        dh[o] = h;
        dl[o] = __float2half(v - __half2float(h));
    }
}

// ---------------- softmax: attn fp32 out + P fp16 single ---------------------
__global__ void softmax_kernel(const float* __restrict__ scores,
                               float* __restrict__ attn, __half* __restrict__ P1)
{
    int gwarp = (blockIdx.x * blockDim.x + threadIdx.x) >> 5;
    int lane  = threadIdx.x & 31;
    if (gwarp >= NB * Sdim) return;
    int gb = gwarp >> 9;       // b*4+h
    int s  = gwarp & 511;
    int b  = gb >> 2;
    int h  = gb & 3;

    const float* row = scores + ((size_t)gb * Sdim + s) * Sdim;
    float vals[16];
    float mx = -1e30f;
#pragma unroll
    for (int i = 0; i < 16; i++) {
        vals[i] = row[lane + i * 32];
        mx = fmaxf(mx, vals[i]);
    }
#pragma unroll
    for (int o = 16; o > 0; o >>= 1) mx = fmaxf(mx, __shfl_xor_sync(0xffffffffu, mx, o));
    float sum = 0.f;
#pragma unroll
    for (int i = 0; i < 16; i++) {
        vals[i] = expf(vals[i] - mx);
        sum += vals[i];
    }
#pragma unroll
    for (int o = 16; o > 0; o >>= 1) sum += __shfl_xor_sync(0xffffffffu, sum, o);
    float inv = 1.f / sum;

    float* arow = attn + (((size_t)b * Sdim + s) * Hdim + h) * HDdim;
    __half* prow = P1 + ((size_t)gb * Sdim + s) * Sdim;
#pragma unroll
    for (int i = 0; i < 16; i++) {
        float p = vals[i] * inv;
        arow[lane + i * 32] = p;
        prow[lane + i * 32] = __float2half(p);
    }
}

// ---------------- launch -----------------------------------------------------
extern "C" void kernel_launch(void* const* d_in, const int* in_sizes, int n_in,
                              void* d_out, int out_size)
{
    const float* q  = (const float*)d_in[0];
    const float* k  = (const float*)d_in[1];
    const float* v  = (const float*)d_in[2];
    const float* Wq = (const float*)d_in[3];
    const float* Wk = (const float*)d_in[4];
    const float* Wv = (const float*)d_in[5];
    const float* Wo = (const float*)d_in[6];
    float* out = (float*)d_out;

    __half *Act, *Whi, *Wlo, *Q1, *Khi, *Klo, *Vthi, *Vtlo, *P1, *C1;
    float *Vh, *Sc, *At;
    cudaGetSymbolAddress((void**)&Act, g_Act);
    cudaGetSymbolAddress((void**)&Whi, g_Whi);   cudaGetSymbolAddress((void**)&Wlo, g_Wlo);
    cudaGetSymbolAddress((void**)&Q1, g_Q1);
    cudaGetSymbolAddress((void**)&Khi, g_Khi);   cudaGetSymbolAddress((void**)&Klo, g_Klo);
    cudaGetSymbolAddress((void**)&Vh, g_Vh);
    cudaGetSymbolAddress((void**)&Vthi, g_Vthi); cudaGetSymbolAddress((void**)&Vtlo, g_Vtlo);
    cudaGetSymbolAddress((void**)&Sc, g_scores); cudaGetSymbolAddress((void**)&At, g_attn_fb);
    cudaGetSymbolAddress((void**)&P1, g_P1);     cudaGetSymbolAddress((void**)&C1, g_C1);

    const long MAIN_OUT = (long)Mrows * Ddim;
    float* attn_out = ((long)out_size >= 2 * MAIN_OUT) ? (out + MAIN_OUT) : At;

    cudaFuncSetAttribute(hgemm, cudaFuncAttributeMaxDynamicSharedMemorySize, GEMM_SMEM);

    const int nAct4 = (int)(ACT_ELEMS / 4);
    const int nW4   = (int)(W_ELEMS / 4);
    dim3 cblk(256);
    dim3 gWCvt(nW4 / 256);
    dim3 gActCvt(nAct4 / 256, 1, 3);
    dim3 blk(512);

    // weight conversions (hi/lo)
    cvt_w<<<gWCvt, cblk>>>(Wq, Whi + 0 * W_ELEMS, Wlo + 0 * W_ELEMS, nW4);
    cvt_w<<<gWCvt, cblk>>>(Wk, Whi + 1 * W_ELEMS, Wlo + 1 * W_ELEMS, nW4);
    cvt_w<<<gWCvt, cblk>>>(Wv, Whi + 2 * W_ELEMS, Wlo + 2 * W_ELEMS, nW4);
    cvt_w<<<gWCvt, cblk>>>(Wo, Whi + 3 * W_ELEMS, Wlo + 3 * W_ELEMS, nW4);
    // activation conversion (single fp16)
    cvt_acts<<<gActCvt, cblk>>>(q, k, v, Act, nAct4);

    // fused Q/K/V projection
    {
        HArgs a;
        a.A = Act; a.Bhi = Whi; a.Blo = Wlo;
        a.K = Ddim; a.ldc = Ddim;
        a.bsA = ACT_ELEMS; a.bsB = W_ELEMS; a.bsC = 0;
        a.Cf = Vh; a.Ch = Q1; a.Khi = Khi; a.Klo = Klo;
        a.alpha = 1.0f; a.mode = EP_QKV3;
        dim3 grid(Ddim / 256, Mrows / 128, 3);    // 8 x 64 x 3
        hgemm<<<grid, blk, GEMM_SMEM>>>(a);
    }
    // V transpose + limb split
    {
        dim3 tb(32, 8), tg(Sdim / 32, HDdim / 32, NB);
        vtrans_kernel<<<tg, tb>>>(Vh, Vthi, Vtlo);
    }
    // scores = Q K^T / sqrt(hd)
    {
        HArgs a;
        a.A = Q1; a.Bhi = Khi; a.Blo = Klo;
        a.K = HDdim; a.ldc = Sdim;
        a.bsA = HEAD_ELEMS; a.bsB = HEAD_ELEMS; a.bsC = HEAD_ELEMS;
        a.Cf = Sc; a.Ch = nullptr; a.Khi = nullptr; a.Klo = nullptr;
        a.alpha = 0.044194173824159223f;
        a.mode = EP_F32;
        dim3 grid(Sdim / 256, Sdim / 128, NB);    // 2 x 4 x 64
        hgemm<<<grid, blk, GEMM_SMEM>>>(a);
    }
    // softmax -> attn output + P fp16
    softmax_kernel<<<(NB * Sdim * 32) / 256, 256>>>(Sc, attn_out, P1);
    // context = P V^T -> C1 (b,h,s,d) fp16 single
    {
        HArgs a;
        a.A = P1; a.Bhi = Vthi; a.Blo = Vtlo;
        a.K = Sdim; a.ldc = HDdim;
        a.bsA = HEAD_ELEMS; a.bsB = HEAD_ELEMS; a.bsC = HEAD_ELEMS;
        a.Cf = nullptr; a.Ch = C1; a.Khi = nullptr; a.Klo = nullptr;
        a.alpha = 1.0f; a.mode = EP_HALF;
        dim3 grid(HDdim / 256, Sdim / 128, NB);   // 2 x 4 x 64
        hgemm<<<grid, blk, GEMM_SMEM>>>(a);
    }
    // output = C @ Wo^T
    {
        HArgs a;
        a.A = C1; a.Bhi = Whi + 3 * W_ELEMS; a.Blo = Wlo + 3 * W_ELEMS;
        a.K = Ddim; a.ldc = Ddim;
        a.bsA = 0; a.bsB = 0; a.bsC = 0;
        a.Cf = out; a.Ch = nullptr; a.Khi = nullptr; a.Klo = nullptr;
        a.alpha = 1.0f; a.mode = EP_F32;
        dim3 grid(Ddim / 256, Mrows / 128, 1);    // 8 x 64
        hgemm<<<grid, blk, GEMM_SMEM>>>(a);
    }
}

// round 8
// speedup vs baseline: 3.7170x; 1.0643x over previous
#include <cuda_runtime.h>
#include <cuda_fp16.h>
#include <stdint.h>
#include <math.h>

// Problem constants
#define Sdim 512
#define Bdim 16
#define Ddim 2048
#define Hdim 4
#define HDdim 512
#define NB 64
#define Mrows 8192
#define HEAD_ELEMS (Sdim * HDdim)          // 262144
#define ACT_ELEMS ((size_t)Mrows * Ddim)   // 16777216
#define W_ELEMS ((size_t)Ddim * Ddim)      // 4194304

// ---------------- scratch (device globals; no allocation allowed) ----------
__device__ __half g_Act[3 * ACT_ELEMS];            // activations fp16
__device__ __half g_W[4 * W_ELEMS];                // weights fp16
__device__ __half g_Q1[(size_t)NB * HEAD_ELEMS];   // Q head-permuted fp16
__device__ __half g_K1[(size_t)NB * HEAD_ELEMS];   // K head-permuted fp16
__device__ float  g_Vh[(size_t)NB * HEAD_ELEMS];   // V head-permuted fp32
__device__ __half g_Vt[(size_t)NB * HEAD_ELEMS];   // V transposed fp16
__device__ float  g_scores[(size_t)NB * HEAD_ELEMS];
__device__ float  g_attn_fb[(size_t)NB * HEAD_ELEMS];
__device__ __half g_P1[(size_t)NB * HEAD_ELEMS];   // softmax probs fp16
__device__ __half g_C1[ACT_ELEMS];                 // context fp16

// ---------------- PTX helpers ------------------------------------------------
__device__ __forceinline__ uint32_t smem_u32(const void* p) {
    uint32_t a;
    asm("{ .reg .u64 t; cvta.to.shared.u64 t, %1; cvt.u32.u64 %0, t; }" : "=r"(a) : "l"(p));
    return a;
}
#define CP_ASYNC16(dst, src) \
    asm volatile("cp.async.cg.shared.global [%0], [%1], 16;" :: "r"(dst), "l"(src))
#define CP_COMMIT  asm volatile("cp.async.commit_group;" ::: "memory")
#define CP_WAIT1   asm volatile("cp.async.wait_group 1;" ::: "memory")

__device__ __forceinline__ void ldsm4(uint32_t* r, uint32_t addr) {
    asm volatile("ldmatrix.sync.aligned.m8n8.x4.shared.b16 {%0,%1,%2,%3}, [%4];"
                 : "=r"(r[0]), "=r"(r[1]), "=r"(r[2]), "=r"(r[3]) : "r"(addr));
}
__device__ __forceinline__ void mma_f16(float* c, const uint32_t* a, const uint32_t* b) {
    asm volatile(
        "mma.sync.aligned.m16n8k16.row.col.f32.f16.f16.f32 "
        "{%0,%1,%2,%3}, {%4,%5,%6,%7}, {%8,%9}, {%0,%1,%2,%3};"
        : "+f"(c[0]), "+f"(c[1]), "+f"(c[2]), "+f"(c[3])
        : "r"(a[0]), "r"(a[1]), "r"(a[2]), "r"(a[3]), "r"(b[0]), "r"(b[1]));
}
__device__ __forceinline__ void wr_h2(__half* H, size_t off, float a, float b) {
    __half2 h; h.x = __float2half(a); h.y = __float2half(b);
    *(__half2*)(H + off) = h;
}

// ---------------- fp16 single-pass NT GEMM -----------------------------------
// C[M,N] = alpha * A[M,K] * B[N,K]^T ; both operands single fp16, fp32 accum.
// Tile 128x256, BK=32, 512 threads (16 warps, 4m x 4n, warp 32x64).
// 3-stage cp.async pipeline, one __syncthreads per chunk.
#define ROW_B 80                        // 32 fp16 = 64B data + 16 pad
#define A_TILE_B (128 * ROW_B)          // 10240
#define B_TILE_B (256 * ROW_B)          // 20480
#define STAGE_B (A_TILE_B + B_TILE_B)   // 30720
#define NSTAGE 3
#define GEMM_SMEM (NSTAGE * STAGE_B)    // 92160

enum { EP_F32 = 0, EP_HALF = 1, EP_QKV3 = 2 };

// r = s*16 + b, c = h*512 + d  ->  ((b*4+h)*512 + s)*512 + d
__device__ __forceinline__ size_t headperm_idx(int r, int c) {
    int s = r >> 4, bb = r & 15, h = c >> 9, d = c & 511;
    return (((size_t)(bb * Hdim + h) * Sdim + s) * HDdim + d);
}

struct HArgs {
    const __half *A, *B;
    int K, ldc;
    size_t bsA, bsB, bsC;
    float* Cf;                 // EP_F32 dst ; EP_QKV3 z==2 (V, fp32)
    __half* Ch;                // EP_HALF dst ; EP_QKV3 z==0 (Q)
    __half* Ch2;               // EP_QKV3 z==1 (K)
    float alpha;
    int mode;
};

__global__ __launch_bounds__(512, 1)
void hgemm(HArgs g)
{
    extern __shared__ char smraw[];
    const uint32_t sb = smem_u32(smraw);
    const int tid = threadIdx.x;
    const int lane = tid & 31;
    const int wid = tid >> 5;
    const int wm = wid & 3;
    const int wn = wid >> 2;
    const int m0 = blockIdx.y * 128;
    const int n0 = blockIdx.x * 256;
    const size_t z = blockIdx.z;

    const __half* A = g.A + z * g.bsA;
    const __half* B = g.B + z * g.bsB;

    float acc[2][8][4];
#pragma unroll
    for (int i = 0; i < 2; i++)
#pragma unroll
        for (int j = 0; j < 8; j++)
#pragma unroll
            for (int x = 0; x < 4; x++) acc[i][j][x] = 0.f;

    const uint32_t a_mrow = (uint32_t)(wm * 32) + (lane & 15);
    const uint32_t a_kadd = (uint32_t)(((lane >> 4) & 1) << 3);
    const uint32_t b_nrow = (uint32_t)(wn * 64) + (lane & 7) + (((lane >> 4) & 1) << 3);
    const uint32_t b_kadd = (uint32_t)(((lane >> 3) & 1) << 3);

    const int la_row = tid >> 2;
    const int la_cc  = tid & 3;
    const int K = g.K;
    const int NCH = K >> 5;

    auto issue = [&](int ch, int stg) {
        const int kOff = ch * 32;
        const uint32_t stb = sb + (uint32_t)stg * STAGE_B;
        {   // A: 512 chunks, 1/thread
            uint32_t d = stb + (uint32_t)la_row * ROW_B + (uint32_t)la_cc * 16;
            CP_ASYNC16(d, A + (size_t)(m0 + la_row) * K + kOff + la_cc * 8);
        }
#pragma unroll
        for (int j = 0; j < 2; j++) {   // B: 1024 chunks, 2/thread
            int id = tid + j * 512;
            int row = id >> 2;
            int cc = id & 3;
            uint32_t d = stb + A_TILE_B + (uint32_t)row * ROW_B + (uint32_t)cc * 16;
            CP_ASYNC16(d, B + (size_t)(n0 + row) * K + kOff + cc * 8);
        }
        CP_COMMIT;
    };

    auto compute = [&](int stg) {
        const uint32_t stb = sb + (uint32_t)stg * STAGE_B;
        const uint32_t aB = stb;
        const uint32_t bB = stb + A_TILE_B;
#pragma unroll
        for (int ks = 0; ks < 2; ks++) {
            uint32_t af[2][4];
#pragma unroll
            for (int i = 0; i < 2; i++) {
                uint32_t off = (a_mrow + (uint32_t)(i * 16)) * ROW_B +
                               ((uint32_t)(ks * 16) + a_kadd) * 2;
                ldsm4(af[i], aB + off);
            }
#pragma unroll
            for (int g2 = 0; g2 < 4; g2++) {
                uint32_t bf[4];
                uint32_t off = (b_nrow + (uint32_t)(g2 * 16)) * ROW_B +
                               ((uint32_t)(ks * 16) + b_kadd) * 2;
                ldsm4(bf, bB + off);
#pragma unroll
                for (int i = 0; i < 2; i++)
#pragma unroll
                    for (int jj = 0; jj < 2; jj++)
                        mma_f16(acc[i][g2 * 2 + jj], af[i], bf + jj * 2);
            }
        }
    };

    issue(0, 0);
    issue(1, 1);
    for (int ch = 0; ch < NCH; ch++) {
        CP_WAIT1;
        __syncthreads();
        if (ch + 2 < NCH) issue(ch + 2, (ch + 2) % NSTAGE);
        compute(ch % NSTAGE);
    }

    // -------- epilogue --------
    const int quad = lane >> 2, tq = lane & 3;
    const float alpha = g.alpha;
#pragma unroll
    for (int i = 0; i < 2; i++) {
#pragma unroll
        for (int jj = 0; jj < 8; jj++) {
            const int r = m0 + wm * 32 + i * 16 + quad;
            const int c = n0 + wn * 64 + jj * 8 + tq * 2;
            const float v0 = acc[i][jj][0] * alpha;
            const float v1 = acc[i][jj][1] * alpha;
            const float v2 = acc[i][jj][2] * alpha;
            const float v3 = acc[i][jj][3] * alpha;
            if (g.mode == EP_F32) {
                float2 a0; a0.x = v0; a0.y = v1;
                float2 a1; a1.x = v2; a1.y = v3;
                *(float2*)(g.Cf + z * g.bsC + (size_t)r * g.ldc + c) = a0;
                *(float2*)(g.Cf + z * g.bsC + (size_t)(r + 8) * g.ldc + c) = a1;
            } else if (g.mode == EP_HALF) {
                wr_h2(g.Ch, z * g.bsC + (size_t)r * g.ldc + c, v0, v1);
                wr_h2(g.Ch, z * g.bsC + (size_t)(r + 8) * g.ldc + c, v2, v3);
            } else {  // EP_QKV3
                size_t o0 = headperm_idx(r, c), o1 = headperm_idx(r + 8, c);
                if (z == 0) {
                    wr_h2(g.Ch, o0, v0, v1);
                    wr_h2(g.Ch, o1, v2, v3);
                } else if (z == 1) {
                    wr_h2(g.Ch2, o0, v0, v1);
                    wr_h2(g.Ch2, o1, v2, v3);
                } else {
                    float2 a0; a0.x = v0; a0.y = v1;
                    float2 a1; a1.x = v2; a1.y = v3;
                    *(float2*)(g.Cf + o0) = a0;
                    *(float2*)(g.Cf + o1) = a1;
                }
            }
        }
    }
}

// ---------------- fp32 -> fp16 (q,k,v combined, z picks) ---------------------
__global__ void cvt_acts(const float* __restrict__ q, const float* __restrict__ k,
                         const float* __restrict__ v, __half* __restrict__ dst, int n4)
{
    int i = blockIdx.x * blockDim.x + threadIdx.x;
    if (i >= n4) return;
    const int zz = blockIdx.z;
    const float* x = (zz == 0) ? q : (zz == 1) ? k : v;
    float4 vv = ((const float4*)x)[i];
    __half2 h0, h1;
    h0.x = __float2half(vv.x); h0.y = __float2half(vv.y);
    h1.x = __float2half(vv.z); h1.y = __float2half(vv.w);
    __half2* d = (__half2*)(dst + (size_t)zz * ACT_ELEMS);
    d[i * 2 + 0] = h0;
    d[i * 2 + 1] = h1;
}

// ---------------- fp32 -> fp16 (4 weights combined, z picks) -----------------
__global__ void cvt_weights(const float* __restrict__ w0, const float* __restrict__ w1,
                            const float* __restrict__ w2, const float* __restrict__ w3,
                            __half* __restrict__ dst, int n4)
{
    int i = blockIdx.x * blockDim.x + threadIdx.x;
    if (i >= n4) return;
    const int zz = blockIdx.z;
    const float* x = (zz == 0) ? w0 : (zz == 1) ? w1 : (zz == 2) ? w2 : w3;
    float4 vv = ((const float4*)x)[i];
    __half2 h0, h1;
    h0.x = __float2half(vv.x); h0.y = __float2half(vv.y);
    h1.x = __float2half(vv.z); h1.y = __float2half(vv.w);
    __half2* d = (__half2*)(dst + (size_t)zz * W_ELEMS);
    d[i * 2 + 0] = h0;
    d[i * 2 + 1] = h1;
}

// ---------------- V transpose -> fp16: Vh[gb][t][d] -> Vt[gb][d][t] ----------
__global__ void vtrans_kernel(const float* __restrict__ Vh, __half* __restrict__ Vt)
{
    __shared__ float tile[32][33];
    const int gb = blockIdx.z;
    const int t0 = blockIdx.x * 32;
    const int d0 = blockIdx.y * 32;
    const int tx = threadIdx.x, ty = threadIdx.y;   // 32 x 8
    const float* src = Vh + (size_t)gb * HEAD_ELEMS;
#pragma unroll
    for (int i = 0; i < 32; i += 8)
        tile[ty + i][tx] = src[(size_t)(t0 + ty + i) * HDdim + d0 + tx];
    __syncthreads();
    __half* dst = Vt + (size_t)gb * HEAD_ELEMS;
#pragma unroll
    for (int i = 0; i < 32; i += 8)
        dst[(size_t)(d0 + ty + i) * Sdim + t0 + tx] = __float2half(tile[tx][ty + i]);
}

// ---------------- softmax: attn fp32 out + P fp16 ----------------------------
__global__ void softmax_kernel(const float* __restrict__ scores,
                               float* __restrict__ attn, __half* __restrict__ P1)
{
    int gwarp = (blockIdx.x * blockDim.x + threadIdx.x) >> 5;
    int lane  = threadIdx.x & 31;
    if (gwarp >= NB * Sdim) return;
    int gb = gwarp >> 9;       // b*4+h
    int s  = gwarp & 511;
    int b  = gb >> 2;
    int h  = gb & 3;

    const float* row = scores + ((size_t)gb * Sdim + s) * Sdim;
    float vals[16];
    float mx = -1e30f;
#pragma unroll
    for (int i = 0; i < 16; i++) {
        vals[i] = row[lane + i * 32];
        mx = fmaxf(mx, vals[i]);
    }
#pragma unroll
    for (int o = 16; o > 0; o >>= 1) mx = fmaxf(mx, __shfl_xor_sync(0xffffffffu, mx, o));
    float sum = 0.f;
#pragma unroll
    for (int i = 0; i < 16; i++) {
        vals[i] = expf(vals[i] - mx);
        sum += vals[i];
    }
#pragma unroll
    for (int o = 16; o > 0; o >>= 1) sum += __shfl_xor_sync(0xffffffffu, sum, o);
    float inv = 1.f / sum;

    float* arow = attn + (((size_t)b * Sdim + s) * Hdim + h) * HDdim;
    __half* prow = P1 + ((size_t)gb * Sdim + s) * Sdim;
#pragma unroll
    for (int i = 0; i < 16; i++) {
        float p = vals[i] * inv;
        arow[lane + i * 32] = p;
        prow[lane + i * 32] = __float2half(p);
    }
}

// ---------------- launch -----------------------------------------------------
extern "C" void kernel_launch(void* const* d_in, const int* in_sizes, int n_in,
                              void* d_out, int out_size)
{
    const float* q  = (const float*)d_in[0];
    const float* k  = (const float*)d_in[1];
    const float* v  = (const float*)d_in[2];
    const float* Wq = (const float*)d_in[3];
    const float* Wk = (const float*)d_in[4];
    const float* Wv = (const float*)d_in[5];
    const float* Wo = (const float*)d_in[6];
    float* out = (float*)d_out;

    __half *Act, *W, *Q1, *K1, *Vt, *P1, *C1;
    float *Vh, *Sc, *At;
    cudaGetSymbolAddress((void**)&Act, g_Act);
    cudaGetSymbolAddress((void**)&W, g_W);
    cudaGetSymbolAddress((void**)&Q1, g_Q1);
    cudaGetSymbolAddress((void**)&K1, g_K1);
    cudaGetSymbolAddress((void**)&Vh, g_Vh);
    cudaGetSymbolAddress((void**)&Vt, g_Vt);
    cudaGetSymbolAddress((void**)&Sc, g_scores);
    cudaGetSymbolAddress((void**)&At, g_attn_fb);
    cudaGetSymbolAddress((void**)&P1, g_P1);
    cudaGetSymbolAddress((void**)&C1, g_C1);

    const long MAIN_OUT = (long)Mrows * Ddim;
    float* attn_out = ((long)out_size >= 2 * MAIN_OUT) ? (out + MAIN_OUT) : At;

    cudaFuncSetAttribute(hgemm, cudaFuncAttributeMaxDynamicSharedMemorySize, GEMM_SMEM);

    const int nAct4 = (int)(ACT_ELEMS / 4);
    const int nW4   = (int)(W_ELEMS / 4);
    dim3 cblk(256);
    dim3 gWCvt(nW4 / 256, 1, 4);
    dim3 gActCvt(nAct4 / 256, 1, 3);
    dim3 blk(512);

    // conversions (single fp16)
    cvt_weights<<<gWCvt, cblk>>>(Wq, Wk, Wv, Wo, W, nW4);
    cvt_acts<<<gActCvt, cblk>>>(q, k, v, Act, nAct4);

    // fused Q/K/V projection
    {
        HArgs a;
        a.A = Act; a.B = W;
        a.K = Ddim; a.ldc = Ddim;
        a.bsA = ACT_ELEMS; a.bsB = W_ELEMS; a.bsC = 0;
        a.Cf = Vh; a.Ch = Q1; a.Ch2 = K1;
        a.alpha = 1.0f; a.mode = EP_QKV3;
        dim3 grid(Ddim / 256, Mrows / 128, 3);    // 8 x 64 x 3
        hgemm<<<grid, blk, GEMM_SMEM>>>(a);
    }
    // V transpose -> fp16
    {
        dim3 tb(32, 8), tg(Sdim / 32, HDdim / 32, NB);
        vtrans_kernel<<<tg, tb>>>(Vh, Vt);
    }
    // scores = Q K^T / sqrt(hd)
    {
        HArgs a;
        a.A = Q1; a.B = K1;
        a.K = HDdim; a.ldc = Sdim;
        a.bsA = HEAD_ELEMS; a.bsB = HEAD_ELEMS; a.bsC = HEAD_ELEMS;
        a.Cf = Sc; a.Ch = nullptr; a.Ch2 = nullptr;
        a.alpha = 0.044194173824159223f;
        a.mode = EP_F32;
        dim3 grid(Sdim / 256, Sdim / 128, NB);    // 2 x 4 x 64
        hgemm<<<grid, blk, GEMM_SMEM>>>(a);
    }
    // softmax -> attn output + P fp16
    softmax_kernel<<<(NB * Sdim * 32) / 256, 256>>>(Sc, attn_out, P1);
    // context = P V^T -> C1 (b,h,s,d) fp16
    {
        HArgs a;
        a.A = P1; a.B = Vt;
        a.K = Sdim; a.ldc = HDdim;
        a.bsA = HEAD_ELEMS; a.bsB = HEAD_ELEMS; a.bsC = HEAD_ELEMS;
        a.Cf = nullptr; a.Ch = C1; a.Ch2 = nullptr;
        a.alpha = 1.0f; a.mode = EP_HALF;
        dim3 grid(HDdim / 256, Sdim / 128, NB);   // 2 x 4 x 64
        hgemm<<<grid, blk, GEMM_SMEM>>>(a);
    }
    // output = C @ Wo^T
    {
        HArgs a;
        a.A = C1; a.B = W + 3 * W_ELEMS;
        a.K = Ddim; a.ldc = Ddim;
        a.bsA = 0; a.bsB = 0; a.bsC = 0;
        a.Cf = out; a.Ch = nullptr; a.Ch2 = nullptr;
        a.alpha = 1.0f; a.mode = EP_F32;
        dim3 grid(Ddim / 256, Mrows / 128, 1);    // 8 x 64
        hgemm<<<grid, blk, GEMM_SMEM>>>(a);
    }
}

// round 11
// speedup vs baseline: 6.8438x; 1.8412x over previous
#include <cuda_runtime.h>
#include <cuda_fp16.h>
#include <stdint.h>
#include <math.h>

// Problem constants
#define Sdim 512
#define Bdim 16
#define Ddim 2048
#define Hdim 4
#define HDdim 512
#define NB 64
#define Mrows 8192
#define HEAD_ELEMS (Sdim * HDdim)            // 262144
#define ACT_ELEMS ((size_t)Mrows * Ddim)     // 16777216
#define W_ELEMS ((size_t)Ddim * Ddim)        // 4194304
#define ACT_BYTES (ACT_ELEMS * 2)            // 32MB per tensor (fp16)
#define W_BYTES (W_ELEMS * 2)                // 8MB per weight (fp16)
#define HEAD_BYTES ((size_t)HEAD_ELEMS * 2)  // 512KB per head (fp16)

// ---------------- scratch (device globals; no allocation allowed) ----------
__device__ __align__(128) char g_Act[3 * ACT_BYTES];           // QKV GEMM A slabs
__device__ __align__(128) char g_W[4 * W_BYTES];               // weights B slabs
__device__ __align__(128) char g_Q1[(size_t)NB * HEAD_BYTES];  // scores A slabs
__device__ __align__(128) char g_K1[(size_t)NB * HEAD_BYTES];  // scores B slabs
__device__ __align__(128) char g_Vt[(size_t)NB * HEAD_BYTES];  // PV B slabs
__device__ __align__(128) char g_P1[(size_t)NB * HEAD_BYTES];  // PV A slabs
__device__ __align__(128) char g_C1[ACT_BYTES];                // Wo A slabs
__device__ float g_Vh[(size_t)NB * HEAD_ELEMS];
__device__ float g_scores[(size_t)NB * HEAD_ELEMS];
__device__ float g_attn_fb[(size_t)NB * HEAD_ELEMS];

// ---------------- PTX helpers ------------------------------------------------
__device__ __forceinline__ uint32_t smem_u32(const void* p) {
    uint32_t a;
    asm("{ .reg .u64 t; cvta.to.shared.u64 t, %1; cvt.u32.u64 %0, t; }" : "=r"(a) : "l"(p));
    return a;
}
#define MBARRIER_INIT(a, c) \
    asm volatile("mbarrier.init.shared.b64 [%0], %1;" :: "r"((uint32_t)(a)), "r"((uint32_t)(c)) : "memory")
#define MBARRIER_EXPECT_TX(a, bytes) \
    asm volatile("mbarrier.arrive.expect_tx.shared.b64 _, [%0], %1;" \
        :: "r"((uint32_t)(a)), "r"((uint32_t)(bytes)) : "memory")
#define TMA_BULK(dst, src, bytes, mbar) \
    asm volatile("cp.async.bulk.shared::cluster.global.mbarrier::complete_tx::bytes [%0], [%1], %2, [%3];" \
        :: "r"((uint32_t)(dst)), "l"(src), "r"((uint32_t)(bytes)), "r"((uint32_t)(mbar)) : "memory")
#define MBARRIER_WAIT_PARITY(mbar_smem_addr, phase_parity) do { \
    uint32_t _mbar = (uint32_t)(mbar_smem_addr); \
    uint32_t _parity = (uint32_t)(phase_parity); \
    uint32_t _done; \
    asm volatile("{\n\t.reg .pred p;\n\t" \
        "mbarrier.try_wait.parity.acquire.cta.shared::cta.b64 p, [%1], %2;\n\t" \
        "selp.b32 %0, 1, 0, p;\n\t}" : "=r"(_done) : "r"(_mbar), "r"(_parity) : "memory"); \
    if (!_done) { \
        asm volatile("{\n\t.reg .pred P1;\n\t" \
            "WAIT_LOOP_%=:\n\t" \
            "mbarrier.try_wait.parity.acquire.cta.shared::cta.b64 P1, [%0], %1, 0x989680;\n\t" \
            "@P1 bra.uni WAIT_DONE_%=;\n\t" \
            "bra.uni WAIT_LOOP_%=;\n\t" \
            "WAIT_DONE_%=:\n\t}" :: "r"(_mbar), "r"(_parity) : "memory"); \
    } \
} while (0)

__device__ __forceinline__ void ldsm4(uint32_t* r, uint32_t addr) {
    asm volatile("ldmatrix.sync.aligned.m8n8.x4.shared.b16 {%0,%1,%2,%3}, [%4];"
                 : "=r"(r[0]), "=r"(r[1]), "=r"(r[2]), "=r"(r[3]) : "r"(addr));
}
__device__ __forceinline__ void mma_f16(float* c, const uint32_t* a, const uint32_t* b) {
    asm volatile(
        "mma.sync.aligned.m16n8k16.row.col.f32.f16.f16.f32 "
        "{%0,%1,%2,%3}, {%4,%5,%6,%7}, {%8,%9}, {%0,%1,%2,%3};"
        : "+f"(c[0]), "+f"(c[1]), "+f"(c[2]), "+f"(c[3])
        : "r"(a[0]), "r"(a[1]), "r"(a[2]), "r"(a[3]), "r"(b[0]), "r"(b[1]));
}
__device__ __forceinline__ uint32_t pack2(float a, float b) {
    __half2 h; h.x = __float2half(a); h.y = __float2half(b);
    return *(uint32_t*)&h;
}

// ---------------- tiled slab layouts -----------------------------------------
// A slab: [mblk][ch][128 rows][4 x 16B swizzled]  (8KB, contiguous)
// B slab: [nblk][ch][256 rows][4 x 16B swizzled]  (16KB, contiguous)
// swizzle: c16' = c16 ^ ((row>>1)&3) -> conflict-free ldmatrix 8-row phases
__device__ __forceinline__ size_t a_tile_off(int row, int col, int nch) {
    int mblk = row >> 7, ar = row & 127, ch = col >> 5;
    int swz = ((col >> 3) & 3) ^ ((ar >> 1) & 3);
    return ((size_t)(mblk * nch + ch) << 13) + (size_t)(ar * 64 + swz * 16 + (col & 7) * 2);
}
__device__ __forceinline__ size_t b_tile_off(int row, int col, int nch) {
    int nblk = row >> 8, br = row & 255, ch = col >> 5;
    int swz = ((col >> 3) & 3) ^ ((br >> 1) & 3);
    return ((size_t)(nblk * nch + ch) << 14) + (size_t)(br * 64 + swz * 16 + (col & 7) * 2);
}

// ---------------- fp16 GEMM with bulk-copy loads -----------------------------
// C[M,N] = alpha * A[M,K] * B[N,K]^T ; operands in tiled slab layout.
// Tile 128x256, chunk=32 k (A slab 8KB + B slab 16KB per chunk).
// 512 threads (16 warps 4m x 4n, warp 32x64). 4-stage bulk pipeline.
// NOTE: __cluster_dims__(1,1,1) is load-bearing — cp.async.bulk with a
// shared::cluster destination requires a cluster launch (R10 hang).
#define STAGE_B 24576
#define NSTAGE 4
#define GEMM_SMEM (64 + NSTAGE * STAGE_B)    // 98368

enum { EP_F32 = 0, EP_HALF = 1, EP_QKV3 = 2 };

struct HArgs {
    const char *aT, *bT;       // tiled slab bases
    size_t bsA, bsB;           // per-z byte strides
    int nch;                   // K/32
    int ldc;
    size_t bsC;                // per-z element stride (EP_F32)
    float* Cf;                 // EP_F32 dst ; EP_QKV3 z==2 (V fp32)
    char *Ch, *Ch2;            // EP_QKV3: Q1, K1 ; EP_HALF: C1
    float alpha;
    int mode;
};

__global__ __launch_bounds__(512, 1) __cluster_dims__(1, 1, 1)
void hgemm(HArgs g)
{
    extern __shared__ char smraw[];
    const uint32_t sb = smem_u32(smraw);
    const uint32_t mb = sb;                 // 4 mbarriers
    const uint32_t stbase = sb + 64;
    const int tid = threadIdx.x;
    const int lane = tid & 31;
    const int wid = tid >> 5;
    const int wm = wid & 3;
    const int wn = wid >> 2;
    const int m0 = blockIdx.y * 128;
    const int n0 = blockIdx.x * 256;
    const size_t z = blockIdx.z;
    const int nch = g.nch;

    const char* aT = g.aT + z * g.bsA;
    const char* bT = g.bT + z * g.bsB;

    float acc[2][8][4];
#pragma unroll
    for (int i = 0; i < 2; i++)
#pragma unroll
        for (int j = 0; j < 8; j++)
#pragma unroll
            for (int x = 0; x < 4; x++) acc[i][j][x] = 0.f;

    if (tid == 0) {
#pragma unroll
        for (int s = 0; s < NSTAGE; s++) MBARRIER_INIT(mb + s * 8, 1);
    }
    asm volatile("fence.proxy.async.shared::cta;" ::: "memory");
    __syncthreads();

    auto issue = [&](int ch, int st) {
        uint32_t d = stbase + (uint32_t)st * STAGE_B;
        MBARRIER_EXPECT_TX(mb + st * 8, STAGE_B);
        TMA_BULK(d,        aT + ((size_t)((int)blockIdx.y * nch + ch) << 13), 8192,  mb + st * 8);
        TMA_BULK(d + 8192, bT + ((size_t)((int)blockIdx.x * nch + ch) << 14), 16384, mb + st * 8);
    };
    if (tid == 0) { issue(0, 0); issue(1, 1); issue(2, 2); }

    const int a_row_base = wm * 32 + (lane & 15);
    const int a_c16half  = (lane >> 4) & 1;
    const int b_row_base = wn * 64 + (lane & 7) + (((lane >> 4) & 1) << 3);
    const int b_c16half  = (lane >> 3) & 1;

    auto compute = [&](int st) {
        const uint32_t aB = stbase + (uint32_t)st * STAGE_B;
        const uint32_t bB = aB + 8192;
#pragma unroll
        for (int ks = 0; ks < 2; ks++) {
            uint32_t af[2][4];
#pragma unroll
            for (int i = 0; i < 2; i++) {
                int row = a_row_base + i * 16;
                int c16 = (ks * 2 + a_c16half) ^ ((row >> 1) & 3);
                ldsm4(af[i], aB + (uint32_t)(row * 64 + c16 * 16));
            }
#pragma unroll
            for (int g2 = 0; g2 < 4; g2++) {
                uint32_t bf[4];
                int row = b_row_base + g2 * 16;
                int c16 = (ks * 2 + b_c16half) ^ ((row >> 1) & 3);
                ldsm4(bf, bB + (uint32_t)(row * 64 + c16 * 16));
#pragma unroll
                for (int i = 0; i < 2; i++)
#pragma unroll
                    for (int jj = 0; jj < 2; jj++)
                        mma_f16(acc[i][g2 * 2 + jj], af[i], bf + jj * 2);
            }
        }
    };

    uint32_t phases = 0;
    for (int ch = 0; ch < nch; ch++) {
        int st = ch & (NSTAGE - 1);
        MBARRIER_WAIT_PARITY(mb + st * 8, (phases >> st) & 1);
        phases ^= 1u << st;
        __syncthreads();       // all warps done with the stage being refilled
        if (tid == 0 && ch + 3 < nch) issue(ch + 3, (ch + 3) & (NSTAGE - 1));
        compute(st);
    }

    // -------- epilogue --------
    const int quad = lane >> 2, tq = lane & 3;
    const float alpha = g.alpha;
#pragma unroll
    for (int i = 0; i < 2; i++) {
#pragma unroll
        for (int jj = 0; jj < 8; jj++) {
            const int r = m0 + wm * 32 + i * 16 + quad;
            const int c = n0 + wn * 64 + jj * 8 + tq * 2;
            const float v0 = acc[i][jj][0] * alpha;
            const float v1 = acc[i][jj][1] * alpha;
            const float v2 = acc[i][jj][2] * alpha;
            const float v3 = acc[i][jj][3] * alpha;
            if (g.mode == EP_F32) {
                float2 a0; a0.x = v0; a0.y = v1;
                float2 a1; a1.x = v2; a1.y = v3;
                *(float2*)(g.Cf + z * g.bsC + (size_t)r * g.ldc + c) = a0;
                *(float2*)(g.Cf + z * g.bsC + (size_t)(r + 8) * g.ldc + c) = a1;
            } else if (g.mode == EP_HALF) {
                size_t f0 = z * (size_t)HEAD_ELEMS + (size_t)r * HDdim + c;
                size_t f1 = f0 + 8 * HDdim;
                *(uint32_t*)(g.Ch + a_tile_off((int)(f0 >> 11), (int)(f0 & 2047), 64)) = pack2(v0, v1);
                *(uint32_t*)(g.Ch + a_tile_off((int)(f1 >> 11), (int)(f1 & 2047), 64)) = pack2(v2, v3);
            } else {  // EP_QKV3
                int s0 = r >> 4, b0 = r & 15, h = c >> 9, d = c & 511;
                int b1 = (r + 8) & 15;
                int gb0 = b0 * Hdim + h, gb1 = b1 * Hdim + h;
                if (z == 0) {
                    *(uint32_t*)(g.Ch + (size_t)gb0 * HEAD_BYTES + a_tile_off(s0, d, 16)) = pack2(v0, v1);
                    *(uint32_t*)(g.Ch + (size_t)gb1 * HEAD_BYTES + a_tile_off(s0, d, 16)) = pack2(v2, v3);
                } else if (z == 1) {
                    *(uint32_t*)(g.Ch2 + (size_t)gb0 * HEAD_BYTES + b_tile_off(s0, d, 16)) = pack2(v0, v1);
                    *(uint32_t*)(g.Ch2 + (size_t)gb1 * HEAD_BYTES + b_tile_off(s0, d, 16)) = pack2(v2, v3);
                } else {
                    float2 a0; a0.x = v0; a0.y = v1;
                    float2 a1; a1.x = v2; a1.y = v3;
                    *(float2*)(g.Cf + (((size_t)gb0 * Sdim + s0) * HDdim + d)) = a0;
                    *(float2*)(g.Cf + (((size_t)gb1 * Sdim + s0) * HDdim + d)) = a1;
                }
            }
        }
    }
}

// ---------------- fp32 -> fp16 tiled A-slabs (q,k,v) -------------------------
__global__ void cvt_acts(const float* __restrict__ q, const float* __restrict__ k,
                         const float* __restrict__ v, char* __restrict__ dst, int n8)
{
    int i = blockIdx.x * blockDim.x + threadIdx.x;
    if (i >= n8) return;
    const int zz = blockIdx.z;
    const float* x = (zz == 0) ? q : (zz == 1) ? k : v;
    size_t flat = (size_t)i * 8;
    float4 a = ((const float4*)(x + flat))[0];
    float4 b = ((const float4*)(x + flat))[1];
    uint4 u;
    u.x = pack2(a.x, a.y); u.y = pack2(a.z, a.w);
    u.z = pack2(b.x, b.y); u.w = pack2(b.z, b.w);
    int row = (int)(flat >> 11), col = (int)(flat & 2047);
    int mblk = row >> 7, ar = row & 127, ch = col >> 5;
    int swz = ((col >> 3) & 3) ^ ((ar >> 1) & 3);
    size_t off = ((size_t)(mblk * 64 + ch) << 13) + (size_t)(ar * 64 + swz * 16);
    *(uint4*)(dst + (size_t)zz * ACT_BYTES + off) = u;
}

// ---------------- fp32 -> fp16 tiled B-slabs (weights) -----------------------
__global__ void cvt_weights(const float* __restrict__ w0, const float* __restrict__ w1,
                            const float* __restrict__ w2, const float* __restrict__ w3,
                            char* __restrict__ dst, int n8)
{
    int i = blockIdx.x * blockDim.x + threadIdx.x;
    if (i >= n8) return;
    const int zz = blockIdx.z;
    const float* x = (zz == 0) ? w0 : (zz == 1) ? w1 : (zz == 2) ? w2 : w3;
    size_t flat = (size_t)i * 8;
    float4 a = ((const float4*)(x + flat))[0];
    float4 b = ((const float4*)(x + flat))[1];
    uint4 u;
    u.x = pack2(a.x, a.y); u.y = pack2(a.z, a.w);
    u.z = pack2(b.x, b.y); u.w = pack2(b.z, b.w);
    int row = (int)(flat >> 11), col = (int)(flat & 2047);
    int nblk = row >> 8, br = row & 255, ch = col >> 5;
    int swz = ((col >> 3) & 3) ^ ((br >> 1) & 3);
    size_t off = ((size_t)(nblk * 64 + ch) << 14) + (size_t)(br * 64 + swz * 16);
    *(uint4*)(dst + (size_t)zz * W_BYTES + off) = u;
}

// ---------------- V transpose -> tiled B-slabs for PV ------------------------
__global__ void vtrans_kernel(const float* __restrict__ Vh, char* __restrict__ VtT)
{
    __shared__ float tile[64][33];
    const int gb = blockIdx.z;
    const int t0 = blockIdx.x * 64;
    const int d0 = blockIdx.y * 32;
    const int tx = threadIdx.x, ty = threadIdx.y;   // 32 x 8
    const float* src = Vh + (size_t)gb * HEAD_ELEMS;
#pragma unroll
    for (int i = 0; i < 8; i++)
        tile[ty + i * 8][tx] = src[(size_t)(t0 + ty + i * 8) * HDdim + d0 + tx];
    __syncthreads();
    int u = ty * 32 + tx;
    int dl = u & 31, tg = u >> 5;
    int d = d0 + dl, t = t0 + tg * 8;
    uint4 o;
    o.x = pack2(tile[tg * 8 + 0][dl], tile[tg * 8 + 1][dl]);
    o.y = pack2(tile[tg * 8 + 2][dl], tile[tg * 8 + 3][dl]);
    o.z = pack2(tile[tg * 8 + 4][dl], tile[tg * 8 + 5][dl]);
    o.w = pack2(tile[tg * 8 + 6][dl], tile[tg * 8 + 7][dl]);
    *(uint4*)(VtT + (size_t)gb * HEAD_BYTES + b_tile_off(d, t, 16)) = o;
}

// ---------------- softmax: attn fp32 + P tiled A-slabs -----------------------
__global__ void softmax_kernel(const float* __restrict__ scores,
                               float* __restrict__ attn, char* __restrict__ P1)
{
    int gwarp = (blockIdx.x * blockDim.x + threadIdx.x) >> 5;
    int lane  = threadIdx.x & 31;
    if (gwarp >= NB * Sdim) return;
    int gb = gwarp >> 9;       // b*4+h
    int s  = gwarp & 511;
    int b  = gb >> 2;
    int h  = gb & 3;

    const float4* row = (const float4*)(scores + ((size_t)gb * Sdim + s) * Sdim);
    float vals[16];
    float mx = -1e30f;
#pragma unroll
    for (int j = 0; j < 4; j++) {
        float4 v = row[lane * 4 + j];
        vals[j * 4 + 0] = v.x; vals[j * 4 + 1] = v.y;
        vals[j * 4 + 2] = v.z; vals[j * 4 + 3] = v.w;
        mx = fmaxf(mx, fmaxf(fmaxf(v.x, v.y), fmaxf(v.z, v.w)));
    }
#pragma unroll
    for (int o = 16; o > 0; o >>= 1) mx = fmaxf(mx, __shfl_xor_sync(0xffffffffu, mx, o));
    float sum = 0.f;
#pragma unroll
    for (int i = 0; i < 16; i++) {
        vals[i] = expf(vals[i] - mx);
        sum += vals[i];
    }
#pragma unroll
    for (int o = 16; o > 0; o >>= 1) sum += __shfl_xor_sync(0xffffffffu, sum, o);
    float inv = 1.f / sum;

    float4* arow = (float4*)(attn + (((size_t)b * Sdim + s) * Hdim + h) * HDdim);
#pragma unroll
    for (int j = 0; j < 4; j++) {
        float4 p;
        p.x = vals[j * 4 + 0] * inv; p.y = vals[j * 4 + 1] * inv;
        p.z = vals[j * 4 + 2] * inv; p.w = vals[j * 4 + 3] * inv;
        arow[lane * 4 + j] = p;
    }
    char* pbase = P1 + (size_t)gb * HEAD_BYTES;
#pragma unroll
    for (int gq = 0; gq < 2; gq++) {
        int t = lane * 16 + gq * 8;
        uint4 o;
        o.x = pack2(vals[gq * 8 + 0] * inv, vals[gq * 8 + 1] * inv);
        o.y = pack2(vals[gq * 8 + 2] * inv, vals[gq * 8 + 3] * inv);
        o.z = pack2(vals[gq * 8 + 4] * inv, vals[gq * 8 + 5] * inv);
        o.w = pack2(vals[gq * 8 + 6] * inv, vals[gq * 8 + 7] * inv);
        *(uint4*)(pbase + a_tile_off(s, t, 16)) = o;
    }
}

// ---------------- launch -----------------------------------------------------
extern "C" void kernel_launch(void* const* d_in, const int* in_sizes, int n_in,
                              void* d_out, int out_size)
{
    const float* q  = (const float*)d_in[0];
    const float* k  = (const float*)d_in[1];
    const float* v  = (const float*)d_in[2];
    const float* Wq = (const float*)d_in[3];
    const float* Wk = (const float*)d_in[4];
    const float* Wv = (const float*)d_in[5];
    const float* Wo = (const float*)d_in[6];
    float* out = (float*)d_out;

    char *Act, *W, *Q1, *K1, *Vt, *P1, *C1;
    float *Vh, *Sc, *At;
    cudaGetSymbolAddress((void**)&Act, g_Act);
    cudaGetSymbolAddress((void**)&W, g_W);
    cudaGetSymbolAddress((void**)&Q1, g_Q1);
    cudaGetSymbolAddress((void**)&K1, g_K1);
    cudaGetSymbolAddress((void**)&Vt, g_Vt);
    cudaGetSymbolAddress((void**)&P1, g_P1);
    cudaGetSymbolAddress((void**)&C1, g_C1);
    cudaGetSymbolAddress((void**)&Vh, g_Vh);
    cudaGetSymbolAddress((void**)&Sc, g_scores);
    cudaGetSymbolAddress((void**)&At, g_attn_fb);

    const long MAIN_OUT = (long)Mrows * Ddim;
    float* attn_out = ((long)out_size >= 2 * MAIN_OUT) ? (out + MAIN_OUT) : At;

    cudaFuncSetAttribute(hgemm, cudaFuncAttributeMaxDynamicSharedMemorySize, GEMM_SMEM);

    const int nAct8 = (int)(ACT_ELEMS / 8);
    const int nW8   = (int)(W_ELEMS / 8);
    dim3 cblk(256);
    dim3 gWCvt(nW8 / 256, 1, 4);
    dim3 gActCvt(nAct8 / 256, 1, 3);
    dim3 blk(512);

    // conversions into tiled slab layouts
    cvt_weights<<<gWCvt, cblk>>>(Wq, Wk, Wv, Wo, W, nW8);
    cvt_acts<<<gActCvt, cblk>>>(q, k, v, Act, nAct8);

    // fused Q/K/V projection
    {
        HArgs a;
        a.aT = Act; a.bT = W;
        a.bsA = ACT_BYTES; a.bsB = W_BYTES;
        a.nch = 64; a.ldc = Ddim; a.bsC = 0;
        a.Cf = Vh; a.Ch = Q1; a.Ch2 = K1;
        a.alpha = 1.0f; a.mode = EP_QKV3;
        dim3 grid(Ddim / 256, Mrows / 128, 3);
        hgemm<<<grid, blk, GEMM_SMEM>>>(a);
    }
    // V transpose -> tiled
    {
        dim3 tb(32, 8), tg(Sdim / 64, HDdim / 32, NB);
        vtrans_kernel<<<tg, tb>>>(Vh, Vt);
    }
    // scores = Q K^T / sqrt(hd)
    {
        HArgs a;
        a.aT = Q1; a.bT = K1;
        a.bsA = HEAD_BYTES; a.bsB = HEAD_BYTES;
        a.nch = 16; a.ldc = Sdim; a.bsC = HEAD_ELEMS;
        a.Cf = Sc; a.Ch = nullptr; a.Ch2 = nullptr;
        a.alpha = 0.044194173824159223f; a.mode = EP_F32;
        dim3 grid(Sdim / 256, Sdim / 128, NB);
        hgemm<<<grid, blk, GEMM_SMEM>>>(a);
    }
    // softmax -> attn output + P tiled
    softmax_kernel<<<(NB * Sdim * 32) / 256, 256>>>(Sc, attn_out, P1);
    // context = P V^T -> C1 tiled (A-slabs for Wo GEMM)
    {
        HArgs a;
        a.aT = P1; a.bT = Vt;
        a.bsA = HEAD_BYTES; a.bsB = HEAD_BYTES;
        a.nch = 16; a.ldc = HDdim; a.bsC = 0;
        a.Cf = nullptr; a.Ch = C1; a.Ch2 = nullptr;
        a.alpha = 1.0f; a.mode = EP_HALF;
        dim3 grid(HDdim / 256, Sdim / 128, NB);
        hgemm<<<grid, blk, GEMM_SMEM>>>(a);
    }
    // output = C @ Wo^T
    {
        HArgs a;
        a.aT = C1; a.bT = W + 3 * W_BYTES;
        a.bsA = 0; a.bsB = 0;
        a.nch = 64; a.ldc = Ddim; a.bsC = 0;
        a.Cf = out; a.Ch = nullptr; a.Ch2 = nullptr;
        a.alpha = 1.0f; a.mode = EP_F32;
        dim3 grid(Ddim / 256, Mrows / 128, 1);
        hgemm<<<grid, blk, GEMM_SMEM>>>(a);
    }
}

// round 13
// speedup vs baseline: 7.4271x; 1.0852x over previous
#include <cuda_runtime.h>
#include <cuda_fp16.h>
#include <stdint.h>
#include <math.h>

// Problem constants
#define Sdim 512
#define Bdim 16
#define Ddim 2048
#define Hdim 4
#define HDdim 512
#define NB 64
#define Mrows 8192
#define HEAD_ELEMS (Sdim * HDdim)            // 262144
#define ACT_ELEMS ((size_t)Mrows * Ddim)     // 16777216
#define W_ELEMS ((size_t)Ddim * Ddim)        // 4194304
#define ACT_BYTES (ACT_ELEMS * 2)
#define W_BYTES (W_ELEMS * 2)
#define HEAD_BYTES ((size_t)HEAD_ELEMS * 2)

// ---------------- scratch (device globals; no allocation allowed) ----------
__device__ __align__(128) char g_Act[3 * ACT_BYTES];
__device__ __align__(128) char g_W[4 * W_BYTES];
__device__ __align__(128) char g_Q1[(size_t)NB * HEAD_BYTES];
__device__ __align__(128) char g_K1[(size_t)NB * HEAD_BYTES];
__device__ __align__(128) char g_Vt[(size_t)NB * HEAD_BYTES];
__device__ __align__(128) char g_P1[(size_t)NB * HEAD_BYTES];
__device__ __align__(128) char g_C1[ACT_BYTES];
__device__ float g_Vh[(size_t)NB * HEAD_ELEMS];
__device__ float g_scores[(size_t)NB * HEAD_ELEMS];
__device__ float g_attn_fb[(size_t)NB * HEAD_ELEMS];

// ---------------- PTX helpers ------------------------------------------------
__device__ __forceinline__ uint32_t smem_u32(const void* p) {
    uint32_t a;
    asm("{ .reg .u64 t; cvta.to.shared.u64 t, %1; cvt.u32.u64 %0, t; }" : "=r"(a) : "l"(p));
    return a;
}
#define MBARRIER_INIT(a, c) \
    asm volatile("mbarrier.init.shared.b64 [%0], %1;" :: "r"((uint32_t)(a)), "r"((uint32_t)(c)) : "memory")
#define MBARRIER_EXPECT_TX(a, bytes) \
    asm volatile("mbarrier.arrive.expect_tx.shared.b64 _, [%0], %1;" \
        :: "r"((uint32_t)(a)), "r"((uint32_t)(bytes)) : "memory")
#define TMA_BULK(dst, src, bytes, mbar) \
    asm volatile("cp.async.bulk.shared::cluster.global.mbarrier::complete_tx::bytes [%0], [%1], %2, [%3];" \
        :: "r"((uint32_t)(dst)), "l"(src), "r"((uint32_t)(bytes)), "r"((uint32_t)(mbar)) : "memory")
#define MBARRIER_WAIT_PARITY(mbar_smem_addr, phase_parity) do { \
    uint32_t _mbar = (uint32_t)(mbar_smem_addr); \
    uint32_t _parity = (uint32_t)(phase_parity); \
    uint32_t _done; \
    asm volatile("{\n\t.reg .pred p;\n\t" \
        "mbarrier.try_wait.parity.acquire.cta.shared::cta.b64 p, [%1], %2;\n\t" \
        "selp.b32 %0, 1, 0, p;\n\t}" : "=r"(_done) : "r"(_mbar), "r"(_parity) : "memory"); \
    if (!_done) { \
        asm volatile("{\n\t.reg .pred P1;\n\t" \
            "WAIT_LOOP_%=:\n\t" \
            "mbarrier.try_wait.parity.acquire.cta.shared::cta.b64 P1, [%0], %1, 0x989680;\n\t" \
            "@P1 bra.uni WAIT_DONE_%=;\n\t" \
            "bra.uni WAIT_LOOP_%=;\n\t" \
            "WAIT_DONE_%=:\n\t}" :: "r"(_mbar), "r"(_parity) : "memory"); \
    } \
} while (0)

__device__ __forceinline__ void ldsm4(uint32_t* r, uint32_t addr) {
    asm volatile("ldmatrix.sync.aligned.m8n8.x4.shared.b16 {%0,%1,%2,%3}, [%4];"
                 : "=r"(r[0]), "=r"(r[1]), "=r"(r[2]), "=r"(r[3]) : "r"(addr));
}
__device__ __forceinline__ void mma_f16(float* c, const uint32_t* a, const uint32_t* b) {
    asm volatile(
        "mma.sync.aligned.m16n8k16.row.col.f32.f16.f16.f32 "
        "{%0,%1,%2,%3}, {%4,%5,%6,%7}, {%8,%9}, {%0,%1,%2,%3};"
        : "+f"(c[0]), "+f"(c[1]), "+f"(c[2]), "+f"(c[3])
        : "r"(a[0]), "r"(a[1]), "r"(a[2]), "r"(a[3]), "r"(b[0]), "r"(b[1]));
}
__device__ __forceinline__ uint32_t pack2(float a, float b) {
    __half2 h; h.x = __float2half(a); h.y = __float2half(b);
    return *(uint32_t*)&h;
}

// ---------------- tiled slab layouts -----------------------------------------
// A slab: [mblk][ch][128 rows][4 x 16B swizzled]  (8KB)
// B slab: [nblk][ch][256 rows][4 x 16B swizzled]  (16KB)
// swizzle: c16' = c16 ^ ((row>>1)&3)
__device__ __forceinline__ size_t a_tile_off(int row, int col, int nch) {
    int mblk = row >> 7, ar = row & 127, ch = col >> 5;
    int swz = ((col >> 3) & 3) ^ ((ar >> 1) & 3);
    return ((size_t)(mblk * nch + ch) << 13) + (size_t)(ar * 64 + swz * 16 + (col & 7) * 2);
}
__device__ __forceinline__ size_t b_tile_off(int row, int col, int nch) {
    int nblk = row >> 8, br = row & 255, ch = col >> 5;
    int swz = ((col >> 3) & 3) ^ ((br >> 1) & 3);
    return ((size_t)(nblk * nch + ch) << 14) + (size_t)(br * 64 + swz * 16 + (col & 7) * 2);
}

// ---------------- fp16 GEMM, bulk loads, 64x64 warp tiles --------------------
// Tile 128x256, chunk=32k. 256 threads = 8 warps (2m x 4n), warp tile 64x64.
// LDSM amplification: A 8KB x4 + B 16KB x2 = 64KB/chunk (was 96KB at 16 warps).
// 6-stage bulk pipeline (prefetch 5). Cluster launch required for bulk copies.
#define STAGE_B 24576
#define NSTAGE 6
#define GEMM_SMEM (64 + NSTAGE * STAGE_B)    // 147520

enum { EP_F32 = 0, EP_HALF = 1, EP_QKV3 = 2 };

struct HArgs {
    const char *aT, *bT;
    size_t bsA, bsB;
    int nch;
    int ldc;
    size_t bsC;
    float* Cf;
    char *Ch, *Ch2;
    float alpha;
    int mode;
};

__global__ __launch_bounds__(256, 1) __cluster_dims__(1, 1, 1)
void hgemm(HArgs g)
{
    extern __shared__ char smraw[];
    const uint32_t sb = smem_u32(smraw);
    const uint32_t mb = sb;                 // 6 mbarriers
    const uint32_t stbase = sb + 64;
    const int tid = threadIdx.x;
    const int lane = tid & 31;
    const int wid = tid >> 5;               // 0..7
    const int wm = wid & 1;                 // 2 m-warps (64 rows each)
    const int wn = wid >> 1;                // 4 n-warps (64 cols each)
    const int m0 = blockIdx.y * 128;
    const int n0 = blockIdx.x * 256;
    const size_t z = blockIdx.z;
    const int nch = g.nch;

    const char* aT = g.aT + z * g.bsA;
    const char* bT = g.bT + z * g.bsB;

    float acc[4][8][4];                     // [m16 tile][n8 tile][frag]
#pragma unroll
    for (int i = 0; i < 4; i++)
#pragma unroll
        for (int j = 0; j < 8; j++)
#pragma unroll
            for (int x = 0; x < 4; x++) acc[i][j][x] = 0.f;

    if (tid == 0) {
#pragma unroll
        for (int s = 0; s < NSTAGE; s++) MBARRIER_INIT(mb + s * 8, 1);
    }
    asm volatile("fence.proxy.async.shared::cta;" ::: "memory");
    __syncthreads();

    auto issue = [&](int ch, int st) {
        uint32_t d = stbase + (uint32_t)st * STAGE_B;
        MBARRIER_EXPECT_TX(mb + st * 8, STAGE_B);
        TMA_BULK(d,        aT + ((size_t)((int)blockIdx.y * nch + ch) << 13), 8192,  mb + st * 8);
        TMA_BULK(d + 8192, bT + ((size_t)((int)blockIdx.x * nch + ch) << 14), 16384, mb + st * 8);
    };
    if (tid == 0) {
        int pre = (nch < NSTAGE - 1) ? nch : (NSTAGE - 1);
        for (int s = 0; s < pre; s++) issue(s, s);
    }

    const int a_row_base = wm * 64 + (lane & 15);
    const int a_c16half  = (lane >> 4) & 1;
    const int b_row_base = wn * 64 + (lane & 7) + (((lane >> 4) & 1) << 3);
    const int b_c16half  = (lane >> 3) & 1;

    auto compute = [&](int st) {
        const uint32_t aB = stbase + (uint32_t)st * STAGE_B;
        const uint32_t bB = aB + 8192;
#pragma unroll
        for (int ks = 0; ks < 2; ks++) {
            uint32_t af[4][4];
#pragma unroll
            for (int i = 0; i < 4; i++) {
                int row = a_row_base + i * 16;
                int c16 = (ks * 2 + a_c16half) ^ ((row >> 1) & 3);
                ldsm4(af[i], aB + (uint32_t)(row * 64 + c16 * 16));
            }
#pragma unroll
            for (int g2 = 0; g2 < 4; g2++) {
                uint32_t bf[4];
                int row = b_row_base + g2 * 16;
                int c16 = (ks * 2 + b_c16half) ^ ((row >> 1) & 3);
                ldsm4(bf, bB + (uint32_t)(row * 64 + c16 * 16));
#pragma unroll
                for (int i = 0; i < 4; i++)
#pragma unroll
                    for (int jj = 0; jj < 2; jj++)
                        mma_f16(acc[i][g2 * 2 + jj], af[i], bf + jj * 2);
            }
        }
    };

    uint32_t phases = 0;
    int st = 0;
    for (int ch = 0; ch < nch; ch++) {
        MBARRIER_WAIT_PARITY(mb + st * 8, (phases >> st) & 1);
        phases ^= 1u << st;
        __syncthreads();       // all warps done with the stage being refilled
        if (tid == 0 && ch + NSTAGE - 1 < nch) {
            int st2 = st - 1; if (st2 < 0) st2 += NSTAGE;
            issue(ch + NSTAGE - 1, st2);
        }
        compute(st);
        if (++st == NSTAGE) st = 0;
    }

    // -------- epilogue --------
    const int quad = lane >> 2, tq = lane & 3;
    const float alpha = g.alpha;
#pragma unroll
    for (int i = 0; i < 4; i++) {
#pragma unroll
        for (int jj = 0; jj < 8; jj++) {
            const int r = m0 + wm * 64 + i * 16 + quad;
            const int c = n0 + wn * 64 + jj * 8 + tq * 2;
            const float v0 = acc[i][jj][0] * alpha;
            const float v1 = acc[i][jj][1] * alpha;
            const float v2 = acc[i][jj][2] * alpha;
            const float v3 = acc[i][jj][3] * alpha;
            if (g.mode == EP_F32) {
                float2 a0; a0.x = v0; a0.y = v1;
                float2 a1; a1.x = v2; a1.y = v3;
                *(float2*)(g.Cf + z * g.bsC + (size_t)r * g.ldc + c) = a0;
                *(float2*)(g.Cf + z * g.bsC + (size_t)(r + 8) * g.ldc + c) = a1;
            } else if (g.mode == EP_HALF) {
                size_t f0 = z * (size_t)HEAD_ELEMS + (size_t)r * HDdim + c;
                size_t f1 = f0 + 8 * HDdim;
                *(uint32_t*)(g.Ch + a_tile_off((int)(f0 >> 11), (int)(f0 & 2047), 64)) = pack2(v0, v1);
                *(uint32_t*)(g.Ch + a_tile_off((int)(f1 >> 11), (int)(f1 & 2047), 64)) = pack2(v2, v3);
            } else {  // EP_QKV3
                int s0 = r >> 4, b0 = r & 15, h = c >> 9, d = c & 511;
                int b1 = (r + 8) & 15;
                int gb0 = b0 * Hdim + h, gb1 = b1 * Hdim + h;
                if (z == 0) {
                    *(uint32_t*)(g.Ch + (size_t)gb0 * HEAD_BYTES + a_tile_off(s0, d, 16)) = pack2(v0, v1);
                    *(uint32_t*)(g.Ch + (size_t)gb1 * HEAD_BYTES + a_tile_off(s0, d, 16)) = pack2(v2, v3);
                } else if (z == 1) {
                    *(uint32_t*)(g.Ch2 + (size_t)gb0 * HEAD_BYTES + b_tile_off(s0, d, 16)) = pack2(v0, v1);
                    *(uint32_t*)(g.Ch2 + (size_t)gb1 * HEAD_BYTES + b_tile_off(s0, d, 16)) = pack2(v2, v3);
                } else {
                    float2 a0; a0.x = v0; a0.y = v1;
                    float2 a1; a1.x = v2; a1.y = v3;
                    *(float2*)(g.Cf + (((size_t)gb0 * Sdim + s0) * HDdim + d)) = a0;
                    *(float2*)(g.Cf + (((size_t)gb1 * Sdim + s0) * HDdim + d)) = a1;
                }
            }
        }
    }
}

// ---------------- fp32 -> fp16 tiled A-slabs (q,k,v) -------------------------
__global__ void cvt_acts(const float* __restrict__ q, const float* __restrict__ k,
                         const float* __restrict__ v, char* __restrict__ dst, int n8)
{
    int i = blockIdx.x * blockDim.x + threadIdx.x;
    if (i >= n8) return;
    const int zz = blockIdx.z;
    const float* x = (zz == 0) ? q : (zz == 1) ? k : v;
    size_t flat = (size_t)i * 8;
    float4 a = ((const float4*)(x + flat))[0];
    float4 b = ((const float4*)(x + flat))[1];
    uint4 u;
    u.x = pack2(a.x, a.y); u.y = pack2(a.z, a.w);
    u.z = pack2(b.x, b.y); u.w = pack2(b.z, b.w);
    int row = (int)(flat >> 11), col = (int)(flat & 2047);
    int mblk = row >> 7, ar = row & 127, ch = col >> 5;
    int swz = ((col >> 3) & 3) ^ ((ar >> 1) & 3);
    size_t off = ((size_t)(mblk * 64 + ch) << 13) + (size_t)(ar * 64 + swz * 16);
    *(uint4*)(dst + (size_t)zz * ACT_BYTES + off) = u;
}

// ---------------- fp32 -> fp16 tiled B-slabs (weights) -----------------------
__global__ void cvt_weights(const float* __restrict__ w0, const float* __restrict__ w1,
                            const float* __restrict__ w2, const float* __restrict__ w3,
                            char* __restrict__ dst, int n8)
{
    int i = blockIdx.x * blockDim.x + threadIdx.x;
    if (i >= n8) return;
    const int zz = blockIdx.z;
    const float* x = (zz == 0) ? w0 : (zz == 1) ? w1 : (zz == 2) ? w2 : w3;
    size_t flat = (size_t)i * 8;
    float4 a = ((const float4*)(x + flat))[0];
    float4 b = ((const float4*)(x + flat))[1];
    uint4 u;
    u.x = pack2(a.x, a.y); u.y = pack2(a.z, a.w);
    u.z = pack2(b.x, b.y); u.w = pack2(b.z, b.w);
    int row = (int)(flat >> 11), col = (int)(flat & 2047);
    int nblk = row >> 8, br = row & 255, ch = col >> 5;
    int swz = ((col >> 3) & 3) ^ ((br >> 1) & 3);
    size_t off = ((size_t)(nblk * 64 + ch) << 14) + (size_t)(br * 64 + swz * 16);
    *(uint4*)(dst + (size_t)zz * W_BYTES + off) = u;
}

// ---------------- V transpose -> tiled B-slabs for PV ------------------------
__global__ void vtrans_kernel(const float* __restrict__ Vh, char* __restrict__ VtT)
{
    __shared__ float tile[64][33];
    const int gb = blockIdx.z;
    const int t0 = blockIdx.x * 64;
    const int d0 = blockIdx.y * 32;
    const int tx = threadIdx.x, ty = threadIdx.y;   // 32 x 8
    const float* src = Vh + (size_t)gb * HEAD_ELEMS;
#pragma unroll
    for (int i = 0; i < 8; i++)
        tile[ty + i * 8][tx] = src[(size_t)(t0 + ty + i * 8) * HDdim + d0 + tx];
    __syncthreads();
    int u = ty * 32 + tx;
    int dl = u & 31, tg = u >> 5;
    int d = d0 + dl, t = t0 + tg * 8;
    uint4 o;
    o.x = pack2(tile[tg * 8 + 0][dl], tile[tg * 8 + 1][dl]);
    o.y = pack2(tile[tg * 8 + 2][dl], tile[tg * 8 + 3][dl]);
    o.z = pack2(tile[tg * 8 + 4][dl], tile[tg * 8 + 5][dl]);
    o.w = pack2(tile[tg * 8 + 6][dl], tile[tg * 8 + 7][dl]);
    *(uint4*)(VtT + (size_t)gb * HEAD_BYTES + b_tile_off(d, t, 16)) = o;
}

// ---------------- softmax: attn fp32 + P tiled A-slabs -----------------------
__global__ void softmax_kernel(const float* __restrict__ scores,
                               float* __restrict__ attn, char* __restrict__ P1)
{
    int gwarp = (blockIdx.x * blockDim.x + threadIdx.x) >> 5;
    int lane  = threadIdx.x & 31;
    if (gwarp >= NB * Sdim) return;
    int gb = gwarp >> 9;       // b*4+h
    int s  = gwarp & 511;
    int b  = gb >> 2;
    int h  = gb & 3;

    const float4* row = (const float4*)(scores + ((size_t)gb * Sdim + s) * Sdim);
    float vals[16];
    float mx = -1e30f;
#pragma unroll
    for (int j = 0; j < 4; j++) {
        float4 v = row[lane * 4 + j];
        vals[j * 4 + 0] = v.x; vals[j * 4 + 1] = v.y;
        vals[j * 4 + 2] = v.z; vals[j * 4 + 3] = v.w;
        mx = fmaxf(mx, fmaxf(fmaxf(v.x, v.y), fmaxf(v.z, v.w)));
    }
#pragma unroll
    for (int o = 16; o > 0; o >>= 1) mx = fmaxf(mx, __shfl_xor_sync(0xffffffffu, mx, o));
    float sum = 0.f;
#pragma unroll
    for (int i = 0; i < 16; i++) {
        vals[i] = expf(vals[i] - mx);
        sum += vals[i];
    }
#pragma unroll
    for (int o = 16; o > 0; o >>= 1) sum += __shfl_xor_sync(0xffffffffu, sum, o);
    float inv = 1.f / sum;

    float4* arow = (float4*)(attn + (((size_t)b * Sdim + s) * Hdim + h) * HDdim);
#pragma unroll
    for (int j = 0; j < 4; j++) {
        float4 p;
        p.x = vals[j * 4 + 0] * inv; p.y = vals[j * 4 + 1] * inv;
        p.z = vals[j * 4 + 2] * inv; p.w = vals[j * 4 + 3] * inv;
        arow[lane * 4 + j] = p;
    }
    char* pbase = P1 + (size_t)gb * HEAD_BYTES;
#pragma unroll
    for (int gq = 0; gq < 2; gq++) {
        int t = lane * 16 + gq * 8;
        uint4 o;
        o.x = pack2(vals[gq * 8 + 0] * inv, vals[gq * 8 + 1] * inv);
        o.y = pack2(vals[gq * 8 + 2] * inv, vals[gq * 8 + 3] * inv);
        o.z = pack2(vals[gq * 8 + 4] * inv, vals[gq * 8 + 5] * inv);
        o.w = pack2(vals[gq * 8 + 6] * inv, vals[gq * 8 + 7] * inv);
        *(uint4*)(pbase + a_tile_off(s, t, 16)) = o;
    }
}

// ---------------- launch -----------------------------------------------------
extern "C" void kernel_launch(void* const* d_in, const int* in_sizes, int n_in,
                              void* d_out, int out_size)
{
    const float* q  = (const float*)d_in[0];
    const float* k  = (const float*)d_in[1];
    const float* v  = (const float*)d_in[2];
    const float* Wq = (const float*)d_in[3];
    const float* Wk = (const float*)d_in[4];
    const float* Wv = (const float*)d_in[5];
    const float* Wo = (const float*)d_in[6];
    float* out = (float*)d_out;

    char *Act, *W, *Q1, *K1, *Vt, *P1, *C1;
    float *Vh, *Sc, *At;
    cudaGetSymbolAddress((void**)&Act, g_Act);
    cudaGetSymbolAddress((void**)&W, g_W);
    cudaGetSymbolAddress((void**)&Q1, g_Q1);
    cudaGetSymbolAddress((void**)&K1, g_K1);
    cudaGetSymbolAddress((void**)&Vt, g_Vt);
    cudaGetSymbolAddress((void**)&P1, g_P1);
    cudaGetSymbolAddress((void**)&C1, g_C1);
    cudaGetSymbolAddress((void**)&Vh, g_Vh);
    cudaGetSymbolAddress((void**)&Sc, g_scores);
    cudaGetSymbolAddress((void**)&At, g_attn_fb);

    const long MAIN_OUT = (long)Mrows * Ddim;
    float* attn_out = ((long)out_size >= 2 * MAIN_OUT) ? (out + MAIN_OUT) : At;

    cudaFuncSetAttribute(hgemm, cudaFuncAttributeMaxDynamicSharedMemorySize, GEMM_SMEM);

    const int nAct8 = (int)(ACT_ELEMS / 8);
    const int nW8   = (int)(W_ELEMS / 8);
    dim3 cblk(256);
    dim3 gWCvt(nW8 / 256, 1, 4);
    dim3 gActCvt(nAct8 / 256, 1, 3);
    dim3 blk(256);

    cvt_weights<<<gWCvt, cblk>>>(Wq, Wk, Wv, Wo, W, nW8);
    cvt_acts<<<gActCvt, cblk>>>(q, k, v, Act, nAct8);

    // fused Q/K/V projection
    {
        HArgs a;
        a.aT = Act; a.bT = W;
        a.bsA = ACT_BYTES; a.bsB = W_BYTES;
        a.nch = 64; a.ldc = Ddim; a.bsC = 0;
        a.Cf = Vh; a.Ch = Q1; a.Ch2 = K1;
        a.alpha = 1.0f; a.mode = EP_QKV3;
        dim3 grid(Ddim / 256, Mrows / 128, 3);
        hgemm<<<grid, blk, GEMM_SMEM>>>(a);
    }
    // V transpose -> tiled
    {
        dim3 tb(32, 8), tg(Sdim / 64, HDdim / 32, NB);
        vtrans_kernel<<<tg, tb>>>(Vh, Vt);
    }
    // scores = Q K^T / sqrt(hd)
    {
        HArgs a;
        a.aT = Q1; a.bT = K1;
        a.bsA = HEAD_BYTES; a.bsB = HEAD_BYTES;
        a.nch = 16; a.ldc = Sdim; a.bsC = HEAD_ELEMS;
        a.Cf = Sc; a.Ch = nullptr; a.Ch2 = nullptr;
        a.alpha = 0.044194173824159223f; a.mode = EP_F32;
        dim3 grid(Sdim / 256, Sdim / 128, NB);
        hgemm<<<grid, blk, GEMM_SMEM>>>(a);
    }
    // softmax -> attn output + P tiled
    softmax_kernel<<<(NB * Sdim * 32) / 256, 256>>>(Sc, attn_out, P1);
    // context = P V^T -> C1 tiled
    {
        HArgs a;
        a.aT = P1; a.bT = Vt;
        a.bsA = HEAD_BYTES; a.bsB = HEAD_BYTES;
        a.nch = 16; a.ldc = HDdim; a.bsC = 0;
        a.Cf = nullptr; a.Ch = C1; a.Ch2 = nullptr;
        a.alpha = 1.0f; a.mode = EP_HALF;
        dim3 grid(HDdim / 256, Sdim / 128, NB);
        hgemm<<<grid, blk, GEMM_SMEM>>>(a);
    }
    // output = C @ Wo^T
    {
        HArgs a;
        a.aT = C1; a.bT = W + 3 * W_BYTES;
        a.bsA = 0; a.bsB = 0;
        a.nch = 64; a.ldc = Ddim; a.bsC = 0;
        a.Cf = out; a.Ch = nullptr; a.Ch2 = nullptr;
        a.alpha = 1.0f; a.mode = EP_F32;
        dim3 grid(Ddim / 256, Mrows / 128, 1);
        hgemm<<<grid, blk, GEMM_SMEM>>>(a);
    }
}

// round 15
// speedup vs baseline: 8.2056x; 1.1048x over previous
#include <cuda_runtime.h>
#include <cuda_fp16.h>
#include <stdint.h>
#include <math.h>

// Problem constants
#define Sdim 512
#define Bdim 16
#define Ddim 2048
#define Hdim 4
#define HDdim 512
#define NB 64
#define Mrows 8192
#define HEAD_ELEMS (Sdim * HDdim)            // 262144
#define ACT_ELEMS ((size_t)Mrows * Ddim)     // 16777216
#define W_ELEMS ((size_t)Ddim * Ddim)        // 4194304
#define ACT_BYTES (ACT_ELEMS * 2)
#define W_BYTES (W_ELEMS * 2)
#define HEAD_BYTES ((size_t)HEAD_ELEMS * 2)

// ---------------- scratch (device globals; no allocation allowed) ----------
__device__ __align__(128) char g_Act[3 * ACT_BYTES];
__device__ __align__(128) char g_W[4 * W_BYTES];
__device__ __align__(128) char g_Q1[(size_t)NB * HEAD_BYTES];
__device__ __align__(128) char g_K1[(size_t)NB * HEAD_BYTES];
__device__ __align__(128) char g_Vt[(size_t)NB * HEAD_BYTES];
__device__ __align__(128) char g_P1[(size_t)NB * HEAD_BYTES];
__device__ __align__(128) char g_C1[ACT_BYTES];
__device__ float g_Vh[(size_t)NB * HEAD_ELEMS];
__device__ float g_scores[(size_t)NB * HEAD_ELEMS];
__device__ float g_attn_fb[(size_t)NB * HEAD_ELEMS];

// ---------------- PTX helpers ------------------------------------------------
__device__ __forceinline__ uint32_t smem_u32(const void* p) {
    uint32_t a;
    asm("{ .reg .u64 t; cvta.to.shared.u64 t, %1; cvt.u32.u64 %0, t; }" : "=r"(a) : "l"(p));
    return a;
}
#define MBARRIER_INIT(a, c) \
    asm volatile("mbarrier.init.shared.b64 [%0], %1;" :: "r"((uint32_t)(a)), "r"((uint32_t)(c)) : "memory")
#define MBARRIER_ARRIVE(a) \
    asm volatile("mbarrier.arrive.shared.b64 _, [%0];" :: "r"((uint32_t)(a)) : "memory")
#define MBARRIER_EXPECT_TX(a, bytes) \
    asm volatile("mbarrier.arrive.expect_tx.shared.b64 _, [%0], %1;" \
        :: "r"((uint32_t)(a)), "r"((uint32_t)(bytes)) : "memory")
#define TMA_BULK(dst, src, bytes, mbar) \
    asm volatile("cp.async.bulk.shared::cluster.global.mbarrier::complete_tx::bytes [%0], [%1], %2, [%3];" \
        :: "r"((uint32_t)(dst)), "l"(src), "r"((uint32_t)(bytes)), "r"((uint32_t)(mbar)) : "memory")
#define MBARRIER_WAIT_PARITY(mbar_smem_addr, phase_parity) do { \
    uint32_t _mbar = (uint32_t)(mbar_smem_addr); \
    uint32_t _parity = (uint32_t)(phase_parity); \
    uint32_t _done; \
    asm volatile("{\n\t.reg .pred p;\n\t" \
        "mbarrier.try_wait.parity.acquire.cta.shared::cta.b64 p, [%1], %2;\n\t" \
        "selp.b32 %0, 1, 0, p;\n\t}" : "=r"(_done) : "r"(_mbar), "r"(_parity) : "memory"); \
    if (!_done) { \
        asm volatile("{\n\t.reg .pred P1;\n\t" \
            "WAIT_LOOP_%=:\n\t" \
            "mbarrier.try_wait.parity.acquire.cta.shared::cta.b64 P1, [%0], %1, 0x989680;\n\t" \
            "@P1 bra.uni WAIT_DONE_%=;\n\t" \
            "bra.uni WAIT_LOOP_%=;\n\t" \
            "WAIT_DONE_%=:\n\t}" :: "r"(_mbar), "r"(_parity) : "memory"); \
    } \
} while (0)

__device__ __forceinline__ void ldsm4(uint32_t* r, uint32_t addr) {
    asm volatile("ldmatrix.sync.aligned.m8n8.x4.shared.b16 {%0,%1,%2,%3}, [%4];"
                 : "=r"(r[0]), "=r"(r[1]), "=r"(r[2]), "=r"(r[3]) : "r"(addr));
}
__device__ __forceinline__ void mma_f16(float* c, const uint32_t* a, const uint32_t* b) {
    asm volatile(
        "mma.sync.aligned.m16n8k16.row.col.f32.f16.f16.f32 "
        "{%0,%1,%2,%3}, {%4,%5,%6,%7}, {%8,%9}, {%0,%1,%2,%3};"
        : "+f"(c[0]), "+f"(c[1]), "+f"(c[2]), "+f"(c[3])
        : "r"(a[0]), "r"(a[1]), "r"(a[2]), "r"(a[3]), "r"(b[0]), "r"(b[1]));
}
__device__ __forceinline__ uint32_t pack2(float a, float b) {
    __half2 h; h.x = __float2half(a); h.y = __float2half(b);
    return *(uint32_t*)&h;
}

// ---------------- tiled slab layouts -----------------------------------------
// A slab: [mblk][ch][128 rows][4 x 16B swizzled]  (8KB)
// B slab: [nblk][ch][256 rows][4 x 16B swizzled]  (16KB)
// swizzle: c16' = c16 ^ ((row>>1)&3)
__device__ __forceinline__ size_t a_tile_off(int row, int col, int nch) {
    int mblk = row >> 7, ar = row & 127, ch = col >> 5;
    int swz = ((col >> 3) & 3) ^ ((ar >> 1) & 3);
    return ((size_t)(mblk * nch + ch) << 13) + (size_t)(ar * 64 + swz * 16 + (col & 7) * 2);
}
__device__ __forceinline__ size_t b_tile_off(int row, int col, int nch) {
    int nblk = row >> 8, br = row & 255, ch = col >> 5;
    int swz = ((col >> 3) & 3) ^ ((br >> 1) & 3);
    return ((size_t)(nblk * nch + ch) << 14) + (size_t)(br * 64 + swz * 16 + (col & 7) * 2);
}

// ---------------- fp16 GEMM, bulk loads, producer/consumer mbarriers ---------
// Tile 128x256, chunk=32k. 256 threads = 8 warps (2m x 4n), warp tile 64x64.
// 6-stage bulk pipeline. Per-stage FULL (tx, count=1) + EMPTY (count=8) barriers;
// no __syncthreads in the mainloop — only tid0 (producer) waits on EMPTY, each
// warp's lane0 arrives after computing a stage. Cluster launch is load-bearing
// for cp.async.bulk (R10 hang).
#define STAGE_B 24576
#define NSTAGE 6
#define GEMM_SMEM (128 + NSTAGE * STAGE_B)    // 147584

enum { EP_F32 = 0, EP_HALF = 1, EP_QKV3 = 2 };

struct HArgs {
    const char *aT, *bT;
    size_t bsA, bsB;
    int nch;
    int ldc;
    size_t bsC;
    float* Cf;
    char *Ch, *Ch2;
    float alpha;
    int mode;
};

__global__ __launch_bounds__(256, 1) __cluster_dims__(1, 1, 1)
void hgemm(HArgs g)
{
    extern __shared__ char smraw[];
    const uint32_t sb = smem_u32(smraw);
    const uint32_t mbF = sb;                // 6 full barriers
    const uint32_t mbE = sb + 48;           // 6 empty barriers
    const uint32_t stbase = sb + 128;
    const int tid = threadIdx.x;
    const int lane = tid & 31;
    const int wid = tid >> 5;               // 0..7
    const int wm = wid & 1;                 // 2 m-warps
    const int wn = wid >> 1;                // 4 n-warps
    const int m0 = blockIdx.y * 128;
    const int n0 = blockIdx.x * 256;
    const size_t z = blockIdx.z;
    const int nch = g.nch;

    const char* aT = g.aT + z * g.bsA;
    const char* bT = g.bT + z * g.bsB;

    float acc[4][8][4];
#pragma unroll
    for (int i = 0; i < 4; i++)
#pragma unroll
        for (int j = 0; j < 8; j++)
#pragma unroll
            for (int x = 0; x < 4; x++) acc[i][j][x] = 0.f;

    if (tid == 0) {
#pragma unroll
        for (int s = 0; s < NSTAGE; s++) {
            MBARRIER_INIT(mbF + s * 8, 1);
            MBARRIER_INIT(mbE + s * 8, 8);
        }
    }
    asm volatile("fence.proxy.async.shared::cta;" ::: "memory");
    __syncthreads();

    auto issue = [&](int ch, int st) {
        uint32_t d = stbase + (uint32_t)st * STAGE_B;
        MBARRIER_EXPECT_TX(mbF + st * 8, STAGE_B);
        TMA_BULK(d,        aT + ((size_t)((int)blockIdx.y * nch + ch) << 13), 8192,  mbF + st * 8);
        TMA_BULK(d + 8192, bT + ((size_t)((int)blockIdx.x * nch + ch) << 14), 16384, mbF + st * 8);
    };
    if (tid == 0) {
        int pre = (nch < NSTAGE - 1) ? nch : (NSTAGE - 1);
        for (int s = 0; s < pre; s++) issue(s, s);
    }

    const int a_row_base = wm * 64 + (lane & 15);
    const int a_c16half  = (lane >> 4) & 1;
    const int b_row_base = wn * 64 + (lane & 7) + (((lane >> 4) & 1) << 3);
    const int b_c16half  = (lane >> 3) & 1;

    auto compute = [&](int st) {
        const uint32_t aB = stbase + (uint32_t)st * STAGE_B;
        const uint32_t bB = aB + 8192;
#pragma unroll
        for (int ks = 0; ks < 2; ks++) {
            uint32_t af[4][4];
#pragma unroll
            for (int i = 0; i < 4; i++) {
                int row = a_row_base + i * 16;
                int c16 = (ks * 2 + a_c16half) ^ ((row >> 1) & 3);
                ldsm4(af[i], aB + (uint32_t)(row * 64 + c16 * 16));
            }
#pragma unroll
            for (int g2 = 0; g2 < 4; g2++) {
                uint32_t bf[4];
                int row = b_row_base + g2 * 16;
                int c16 = (ks * 2 + b_c16half) ^ ((row >> 1) & 3);
                ldsm4(bf, bB + (uint32_t)(row * 64 + c16 * 16));
#pragma unroll
                for (int i = 0; i < 4; i++)
#pragma unroll
                    for (int jj = 0; jj < 2; jj++)
                        mma_f16(acc[i][g2 * 2 + jj], af[i], bf + jj * 2);
            }
        }
    };

    uint32_t phases = 0;    // full-barrier parity per slot
    uint32_t ephases = 0;   // empty-barrier parity per slot (producer only)
    int st = 0;
    for (int ch = 0; ch < nch; ch++) {
        MBARRIER_WAIT_PARITY(mbF + st * 8, (phases >> st) & 1);
        phases ^= 1u << st;
        if (tid == 0 && ch + NSTAGE - 1 < nch) {
            int sr = st - 1; if (sr < 0) sr += NSTAGE;
            if (ch >= 1) {   // slot sr was last computed at chunk ch-1; wait for all warps
                MBARRIER_WAIT_PARITY(mbE + sr * 8, (ephases >> sr) & 1);
                ephases ^= 1u << sr;
            }
            issue(ch + NSTAGE - 1, sr);
        }
        compute(st);
        if (lane == 0) MBARRIER_ARRIVE(mbE + st * 8);
        if (++st == NSTAGE) st = 0;
    }

    // -------- epilogue --------
    const int quad = lane >> 2, tq = lane & 3;
    const float alpha = g.alpha;
#pragma unroll
    for (int i = 0; i < 4; i++) {
#pragma unroll
        for (int jj = 0; jj < 8; jj++) {
            const int r = m0 + wm * 64 + i * 16 + quad;
            const int c = n0 + wn * 64 + jj * 8 + tq * 2;
            const float v0 = acc[i][jj][0] * alpha;
            const float v1 = acc[i][jj][1] * alpha;
            const float v2 = acc[i][jj][2] * alpha;
            const float v3 = acc[i][jj][3] * alpha;
            if (g.mode == EP_F32) {
                float2 a0; a0.x = v0; a0.y = v1;
                float2 a1; a1.x = v2; a1.y = v3;
                *(float2*)(g.Cf + z * g.bsC + (size_t)r * g.ldc + c) = a0;
                *(float2*)(g.Cf + z * g.bsC + (size_t)(r + 8) * g.ldc + c) = a1;
            } else if (g.mode == EP_HALF) {
                size_t f0 = z * (size_t)HEAD_ELEMS + (size_t)r * HDdim + c;
                size_t f1 = f0 + 8 * HDdim;
                *(uint32_t*)(g.Ch + a_tile_off((int)(f0 >> 11), (int)(f0 & 2047), 64)) = pack2(v0, v1);
                *(uint32_t*)(g.Ch + a_tile_off((int)(f1 >> 11), (int)(f1 & 2047), 64)) = pack2(v2, v3);
            } else {  // EP_QKV3
                int s0 = r >> 4, b0 = r & 15, h = c >> 9, d = c & 511;
                int b1 = (r + 8) & 15;
                int gb0 = b0 * Hdim + h, gb1 = b1 * Hdim + h;
                if (z == 0) {
                    *(uint32_t*)(g.Ch + (size_t)gb0 * HEAD_BYTES + a_tile_off(s0, d, 16)) = pack2(v0, v1);
                    *(uint32_t*)(g.Ch + (size_t)gb1 * HEAD_BYTES + a_tile_off(s0, d, 16)) = pack2(v2, v3);
                } else if (z == 1) {
                    *(uint32_t*)(g.Ch2 + (size_t)gb0 * HEAD_BYTES + b_tile_off(s0, d, 16)) = pack2(v0, v1);
                    *(uint32_t*)(g.Ch2 + (size_t)gb1 * HEAD_BYTES + b_tile_off(s0, d, 16)) = pack2(v2, v3);
                } else {
                    float2 a0; a0.x = v0; a0.y = v1;
                    float2 a1; a1.x = v2; a1.y = v3;
                    *(float2*)(g.Cf + (((size_t)gb0 * Sdim + s0) * HDdim + d)) = a0;
                    *(float2*)(g.Cf + (((size_t)gb1 * Sdim + s0) * HDdim + d)) = a1;
                }
            }
        }
    }
}

// ---------------- fp32 -> fp16 tiled A-slabs (q,k,v) -------------------------
__global__ void cvt_acts(const float* __restrict__ q, const float* __restrict__ k,
                         const float* __restrict__ v, char* __restrict__ dst, int n8)
{
    int i = blockIdx.x * blockDim.x + threadIdx.x;
    if (i >= n8) return;
    const int zz = blockIdx.z;
    const float* x = (zz == 0) ? q : (zz == 1) ? k : v;
    size_t flat = (size_t)i * 8;
    float4 a = ((const float4*)(x + flat))[0];
    float4 b = ((const float4*)(x + flat))[1];
    uint4 u;
    u.x = pack2(a.x, a.y); u.y = pack2(a.z, a.w);
    u.z = pack2(b.x, b.y); u.w = pack2(b.z, b.w);
    int row = (int)(flat >> 11), col = (int)(flat & 2047);
    int mblk = row >> 7, ar = row & 127, ch = col >> 5;
    int swz = ((col >> 3) & 3) ^ ((ar >> 1) & 3);
    size_t off = ((size_t)(mblk * 64 + ch) << 13) + (size_t)(ar * 64 + swz * 16);
    *(uint4*)(dst + (size_t)zz * ACT_BYTES + off) = u;
}

// ---------------- fp32 -> fp16 tiled B-slabs (weights) -----------------------
__global__ void cvt_weights(const float* __restrict__ w0, const float* __restrict__ w1,
                            const float* __restrict__ w2, const float* __restrict__ w3,
                            char* __restrict__ dst, int n8)
{
    int i = blockIdx.x * blockDim.x + threadIdx.x;
    if (i >= n8) return;
    const int zz = blockIdx.z;
    const float* x = (zz == 0) ? w0 : (zz == 1) ? w1 : (zz == 2) ? w2 : w3;
    size_t flat = (size_t)i * 8;
    float4 a = ((const float4*)(x + flat))[0];
    float4 b = ((const float4*)(x + flat))[1];
    uint4 u;
    u.x = pack2(a.x, a.y); u.y = pack2(a.z, a.w);
    u.z = pack2(b.x, b.y); u.w = pack2(b.z, b.w);
    int row = (int)(flat >> 11), col = (int)(flat & 2047);
    int nblk = row >> 8, br = row & 255, ch = col >> 5;
    int swz = ((col >> 3) & 3) ^ ((br >> 1) & 3);
    size_t off = ((size_t)(nblk * 64 + ch) << 14) + (size_t)(br * 64 + swz * 16);
    *(uint4*)(dst + (size_t)zz * W_BYTES + off) = u;
}

// ---------------- V transpose -> tiled B-slabs for PV ------------------------
__global__ void vtrans_kernel(const float* __restrict__ Vh, char* __restrict__ VtT)
{
    __shared__ float tile[64][33];
    const int gb = blockIdx.z;
    const int t0 = blockIdx.x * 64;
    const int d0 = blockIdx.y * 32;
    const int tx = threadIdx.x, ty = threadIdx.y;   // 32 x 8
    const float* src = Vh + (size_t)gb * HEAD_ELEMS;
#pragma unroll
    for (int i = 0; i < 8; i++)
        tile[ty + i * 8][tx] = src[(size_t)(t0 + ty + i * 8) * HDdim + d0 + tx];
    __syncthreads();
    int u = ty * 32 + tx;
    int dl = u & 31, tg = u >> 5;
    int d = d0 + dl, t = t0 + tg * 8;
    uint4 o;
    o.x = pack2(tile[tg * 8 + 0][dl], tile[tg * 8 + 1][dl]);
    o.y = pack2(tile[tg * 8 + 2][dl], tile[tg * 8 + 3][dl]);
    o.z = pack2(tile[tg * 8 + 4][dl], tile[tg * 8 + 5][dl]);
    o.w = pack2(tile[tg * 8 + 6][dl], tile[tg * 8 + 7][dl]);
    *(uint4*)(VtT + (size_t)gb * HEAD_BYTES + b_tile_off(d, t, 16)) = o;
}

// ---------------- softmax: attn fp32 + P tiled A-slabs -----------------------
__global__ void softmax_kernel(const float* __restrict__ scores,
                               float* __restrict__ attn, char* __restrict__ P1)
{
    int gwarp = (blockIdx.x * blockDim.x + threadIdx.x) >> 5;
    int lane  = threadIdx.x & 31;
    if (gwarp >= NB * Sdim) return;
    int gb = gwarp >> 9;       // b*4+h
    int s  = gwarp & 511;
    int b  = gb >> 2;
    int h  = gb & 3;

    const float4* row = (const float4*)(scores + ((size_t)gb * Sdim + s) * Sdim);
    float vals[16];
    float mx = -1e30f;
#pragma unroll
    for (int j = 0; j < 4; j++) {
        float4 v = row[lane * 4 + j];
        vals[j * 4 + 0] = v.x; vals[j * 4 + 1] = v.y;
        vals[j * 4 + 2] = v.z; vals[j * 4 + 3] = v.w;
        mx = fmaxf(mx, fmaxf(fmaxf(v.x, v.y), fmaxf(v.z, v.w)));
    }
#pragma unroll
    for (int o = 16; o > 0; o >>= 1) mx = fmaxf(mx, __shfl_xor_sync(0xffffffffu, mx, o));
    float sum = 0.f;
#pragma unroll
    for (int i = 0; i < 16; i++) {
        vals[i] = expf(vals[i] - mx);
        sum += vals[i];
    }
#pragma unroll
    for (int o = 16; o > 0; o >>= 1) sum += __shfl_xor_sync(0xffffffffu, sum, o);
    float inv = 1.f / sum;

    float4* arow = (float4*)(attn + (((size_t)b * Sdim + s) * Hdim + h) * HDdim);
#pragma unroll
    for (int j = 0; j < 4; j++) {
        float4 p;
        p.x = vals[j * 4 + 0] * inv; p.y = vals[j * 4 + 1] * inv;
        p.z = vals[j * 4 + 2] * inv; p.w = vals[j * 4 + 3] * inv;
        arow[lane * 4 + j] = p;
    }
    char* pbase = P1 + (size_t)gb * HEAD_BYTES;
#pragma unroll
    for (int gq = 0; gq < 2; gq++) {
        int t = lane * 16 + gq * 8;
        uint4 o;
        o.x = pack2(vals[gq * 8 + 0] * inv, vals[gq * 8 + 1] * inv);
        o.y = pack2(vals[gq * 8 + 2] * inv, vals[gq * 8 + 3] * inv);
        o.z = pack2(vals[gq * 8 + 4] * inv, vals[gq * 8 + 5] * inv);
        o.w = pack2(vals[gq * 8 + 6] * inv, vals[gq * 8 + 7] * inv);
        *(uint4*)(pbase + a_tile_off(s, t, 16)) = o;
    }
}

// ---------------- launch -----------------------------------------------------
extern "C" void kernel_launch(void* const* d_in, const int* in_sizes, int n_in,
                              void* d_out, int out_size)
{
    const float* q  = (const float*)d_in[0];
    const float* k  = (const float*)d_in[1];
    const float* v  = (const float*)d_in[2];
    const float* Wq = (const float*)d_in[3];
    const float* Wk = (const float*)d_in[4];
    const float* Wv = (const float*)d_in[5];
    const float* Wo = (const float*)d_in[6];
    float* out = (float*)d_out;

    char *Act, *W, *Q1, *K1, *Vt, *P1, *C1;
    float *Vh, *Sc, *At;
    cudaGetSymbolAddress((void**)&Act, g_Act);
    cudaGetSymbolAddress((void**)&W, g_W);
    cudaGetSymbolAddress((void**)&Q1, g_Q1);
    cudaGetSymbolAddress((void**)&K1, g_K1);
    cudaGetSymbolAddress((void**)&Vt, g_Vt);
    cudaGetSymbolAddress((void**)&P1, g_P1);
    cudaGetSymbolAddress((void**)&C1, g_C1);
    cudaGetSymbolAddress((void**)&Vh, g_Vh);
    cudaGetSymbolAddress((void**)&Sc, g_scores);
    cudaGetSymbolAddress((void**)&At, g_attn_fb);

    const long MAIN_OUT = (long)Mrows * Ddim;
    float* attn_out = ((long)out_size >= 2 * MAIN_OUT) ? (out + MAIN_OUT) : At;

    cudaFuncSetAttribute(hgemm, cudaFuncAttributeMaxDynamicSharedMemorySize, GEMM_SMEM);

    const int nAct8 = (int)(ACT_ELEMS / 8);
    const int nW8   = (int)(W_ELEMS / 8);
    dim3 cblk(256);
    dim3 gWCvt(nW8 / 256, 1, 4);
    dim3 gActCvt(nAct8 / 256, 1, 3);
    dim3 blk(256);

    cvt_weights<<<gWCvt, cblk>>>(Wq, Wk, Wv, Wo, W, nW8);
    cvt_acts<<<gActCvt, cblk>>>(q, k, v, Act, nAct8);

    // fused Q/K/V projection
    {
        HArgs a;
        a.aT = Act; a.bT = W;
        a.bsA = ACT_BYTES; a.bsB = W_BYTES;
        a.nch = 64; a.ldc = Ddim; a.bsC = 0;
        a.Cf = Vh; a.Ch = Q1; a.Ch2 = K1;
        a.alpha = 1.0f; a.mode = EP_QKV3;
        dim3 grid(Ddim / 256, Mrows / 128, 3);
        hgemm<<<grid, blk, GEMM_SMEM>>>(a);
    }
    // V transpose -> tiled
    {
        dim3 tb(32, 8), tg(Sdim / 64, HDdim / 32, NB);
        vtrans_kernel<<<tg, tb>>>(Vh, Vt);
    }
    // scores = Q K^T / sqrt(hd)
    {
        HArgs a;
        a.aT = Q1; a.bT = K1;
        a.bsA = HEAD_BYTES; a.bsB = HEAD_BYTES;
        a.nch = 16; a.ldc = Sdim; a.bsC = HEAD_ELEMS;
        a.Cf = Sc; a.Ch = nullptr; a.Ch2 = nullptr;
        a.alpha = 0.044194173824159223f; a.mode = EP_F32;
        dim3 grid(Sdim / 256, Sdim / 128, NB);
        hgemm<<<grid, blk, GEMM_SMEM>>>(a);
    }
    // softmax -> attn output + P tiled
    softmax_kernel<<<(NB * Sdim * 32) / 256, 256>>>(Sc, attn_out, P1);
    // context = P V^T -> C1 tiled
    {
        HArgs a;
        a.aT = P1; a.bT = Vt;
        a.bsA = HEAD_BYTES; a.bsB = HEAD_BYTES;
        a.nch = 16; a.ldc = HDdim; a.bsC = 0;
        a.Cf = nullptr; a.Ch = C1; a.Ch2 = nullptr;
        a.alpha = 1.0f; a.mode = EP_HALF;
        dim3 grid(HDdim / 256, Sdim / 128, NB);
        hgemm<<<grid, blk, GEMM_SMEM>>>(a);
    }
    // output = C @ Wo^T
    {
        HArgs a;
        a.aT = C1; a.bT = W + 3 * W_BYTES;
        a.bsA = 0; a.bsB = 0;
        a.nch = 64; a.ldc = Ddim; a.bsC = 0;
        a.Cf = out; a.Ch = nullptr; a.Ch2 = nullptr;
        a.alpha = 1.0f; a.mode = EP_F32;
        dim3 grid(Ddim / 256, Mrows / 128, 1);
        hgemm<<<grid, blk, GEMM_SMEM>>>(a);
    }
}